// round 14
// baseline (speedup 1.0000x reference)
#include <cuda_runtime.h>
#include <cuda_bf16.h>
#include <cuda_fp16.h>
#include <math.h>
#include <float.h>
#include <stdint.h>

#define DIN   128
#define NHEAD 4
#define EPSV  1e-5f
#define SLOPE 0.2f
#define MAXN  50000
#define MAXE  800000
#define MAXT  392            // max M tiles of 128

// ---------------- scratch (static device globals; no allocation) ------------
__device__ __half g_xhh[(size_t)MAXN * DIN];            // h @ W (fp16 messages)
__device__ float  g_h2 [(size_t)MAXN * DIN];            // gat out + residual
__device__ float  g_asrc[(size_t)MAXN * NHEAD];
__device__ float  g_adst[(size_t)MAXN * NHEAD];
__device__ int    g_src [MAXE + MAXN];
__device__ int    g_dst [MAXE + MAXN];
__device__ int    g_col [MAXE + MAXN];                  // CSR: src per slot
__device__ int    g_cnt [MAXN];
__device__ int    g_rowp[MAXN + 1];
__device__ int    g_cur [MAXN];
__device__ int    g_is64;

// bf16 hi/lo A-operand images, pre-swizzled SMEM tile layout:
// [mtile][sel(hi=0,lo=1)][chunk][128 rows x 128 bytes, SW128]   (chunk = 64 k-vals)
__device__ __align__(16) char g_A1[(size_t)MAXT * 2 * 2 * 16384];  // LN1(x),    K=128
__device__ __align__(16) char g_A2[(size_t)MAXT * 2 * 2 * 16384];  // LN2(h2),   K=128
__device__ __align__(16) char g_A3[(size_t)MAXT * 2 * 4 * 16384];  // gelu(ffn1),K=256
// B images: [sel][chunk][N rows x 128 bytes, SW128]  (n-major, k contiguous)
__device__ __align__(16) char g_B1[2 * 2 * 128 * 128];
__device__ __align__(16) char g_B2[2 * 2 * 256 * 128];
__device__ __align__(16) char g_B3[2 * 4 * 128 * 128];

// ---------------- helpers ------------------------------------------------------
#define SWZ(o) ((uint32_t)(o) ^ ((((uint32_t)(o)) >> 3) & 0x70u))

__device__ __forceinline__ uint32_t smem_u32(const void* p) {
    uint32_t a;
    asm("{ .reg .u64 t; cvta.to.shared.u64 t, %1; cvt.u32.u64 %0, t; }" : "=r"(a) : "l"(p));
    return a;
}
__device__ __forceinline__ void ldsm4(uint32_t* r, uint32_t addr) {
    asm volatile("ldmatrix.sync.aligned.m8n8.x4.shared.b16 {%0,%1,%2,%3}, [%4];"
                 : "=r"(r[0]), "=r"(r[1]), "=r"(r[2]), "=r"(r[3]) : "r"(addr));
}
__device__ __forceinline__ void mma16816(float* c, const uint32_t* a, const uint32_t* b) {
    asm volatile("mma.sync.aligned.m16n8k16.row.col.f32.bf16.bf16.f32 "
                 "{%0,%1,%2,%3}, {%4,%5,%6,%7}, {%8,%9}, {%0,%1,%2,%3};"
                 : "+f"(c[0]), "+f"(c[1]), "+f"(c[2]), "+f"(c[3])
                 : "r"(a[0]), "r"(a[1]), "r"(a[2]), "r"(a[3]), "r"(b[0]), "r"(b[1]));
}
__device__ __forceinline__ void cpasync16(uint32_t dst, const void* src) {
    asm volatile("cp.async.cg.shared.global [%0], [%1], 16;" :: "r"(dst), "l"(src) : "memory");
}
__device__ __forceinline__ float warpSum(float v) {
#pragma unroll
    for (int o = 16; o; o >>= 1) v += __shfl_xor_sync(0xffffffffu, v, o);
    return v;
}
__device__ __forceinline__ float geluf(float v) {
    return 0.5f * v * (1.f + erff(v * 0.70710678118654752440f));
}
__device__ __forceinline__ float lrelu(float v) { return v > 0.f ? v : SLOPE * v; }

__device__ __forceinline__ void split2(float v0, float v1, uint32_t& hi, uint32_t& lo) {
    __nv_bfloat16 h0 = __float2bfloat16(v0), h1 = __float2bfloat16(v1);
    __nv_bfloat16 l0 = __float2bfloat16(v0 - __bfloat162float(h0));
    __nv_bfloat16 l1 = __float2bfloat16(v1 - __bfloat162float(h1));
    __nv_bfloat162 hp; hp.x = h0; hp.y = h1;
    __nv_bfloat162 lp; lp.x = l0; lp.y = l1;
    hi = *(uint32_t*)&hp; lo = *(uint32_t*)&lp;
}
__device__ __forceinline__ void split_store8(char* base, size_t hiOff, size_t loOff,
                                             uint32_t off, float4 o) {
    uint32_t h0, l0, h1, l1;
    split2(o.x, o.y, h0, l0);
    split2(o.z, o.w, h1, l1);
    *(uint32_t*)(base + hiOff + off)     = h0;
    *(uint32_t*)(base + hiOff + off + 4) = h1;
    *(uint32_t*)(base + loOff + off)     = l0;
    *(uint32_t*)(base + loOff + off + 4) = l1;
}

// ---------------- detect dtype (1 block; g_cnt zeroed by memsetAsync) ---------
__global__ void detect_kernel(const int* __restrict__ ei32, int E) {
    __shared__ int any;
    if (threadIdx.x == 0) any = 0;
    __syncthreads();
    int samples = min(E, 4096);
    int local = 0;
    for (int k = threadIdx.x; k < samples; k += blockDim.x)
        if (ei32[2 * k + 1] != 0) local = 1;
    if (local) atomicOr(&any, 1);
    __syncthreads();
    if (threadIdx.x == 0) g_is64 = any ? 0 : 1;
}

// convert + degree count: 4 edges per thread for MLP
__global__ void count_kernel(const void* __restrict__ ei, int E, int Et) {
    int base = (blockIdx.x * blockDim.x + threadIdx.x) * 4;
    if (base >= Et) return;
    const int is64 = g_is64;
    int s[4], d[4];
    int cnt = min(4, Et - base);
#pragma unroll
    for (int j = 0; j < 4; j++) {
        if (j >= cnt) break;
        int e = base + j;
        if (e < E) {
            if (is64) {
                const long long* p = (const long long*)ei;
                s[j] = (int)p[e]; d[j] = (int)p[(size_t)E + e];
            } else {
                const int* p = (const int*)ei;
                s[j] = p[e]; d[j] = p[E + e];
            }
        } else { s[j] = d[j] = e - E; }
    }
#pragma unroll
    for (int j = 0; j < 4; j++) {
        if (j >= cnt) break;
        g_src[base + j] = s[j];
        g_dst[base + j] = d[j];
    }
#pragma unroll
    for (int j = 0; j < 4; j++) {
        if (j >= cnt) break;
        atomicAdd(&g_cnt[d[j]], 1);
    }
}

// ---------------- merged scan: each block self-computes its chunk base --------
__global__ void scan_kernel(int n) {
    __shared__ int wsum[8];
    __shared__ int red[8];
    __shared__ int chunkBase;
    int b = blockIdx.x, tid = threadIdx.x;
    int lane = tid & 31, wid = tid >> 5;

    {
        int pre = b * 1024;
        int s = 0;
        for (int i = tid; i < pre; i += 256) s += g_cnt[i];
#pragma unroll
        for (int o = 16; o; o >>= 1) s += __shfl_xor_sync(0xffffffffu, s, o);
        if (lane == 0) red[wid] = s;
        __syncthreads();
        if (tid == 0) {
            int t = 0;
#pragma unroll
            for (int w = 0; w < 8; w++) t += red[w];
            chunkBase = t;
        }
    }

    int i0 = b * 1024 + tid * 4;
    int v[4];
#pragma unroll
    for (int j = 0; j < 4; j++) v[j] = (i0 + j < n) ? g_cnt[i0 + j] : 0;
    int tsum = v[0] + v[1] + v[2] + v[3];
    int incl = tsum;
#pragma unroll
    for (int o = 1; o < 32; o <<= 1) {
        int t = __shfl_up_sync(0xffffffffu, incl, o);
        if (lane >= o) incl += t;
    }
    if (lane == 31) wsum[wid] = incl;
    __syncthreads();
    if (tid == 0) {
        int s = 0;
#pragma unroll
        for (int w = 0; w < 8; w++) { int t = wsum[w]; wsum[w] = s; s += t; }
    }
    __syncthreads();
    int run = chunkBase + wsum[wid] + incl - tsum;
#pragma unroll
    for (int j = 0; j < 4; j++) {
        if (i0 + j < n) { g_rowp[i0 + j] = run; g_cur[i0 + j] = run; }
        run += v[j];
    }
}

// scatter: 4 edges per thread for MLP (independent atomic+store chains)
__global__ void scatter_kernel(int Et) {
    int base = (blockIdx.x * blockDim.x + threadIdx.x) * 4;
    if (base >= Et) return;
    int cnt = min(4, Et - base);
    int d[4], s[4];
#pragma unroll
    for (int j = 0; j < 4; j++) {
        if (j >= cnt) break;
        d[j] = g_dst[base + j];
        s[j] = g_src[base + j];
    }
    int pos[4];
#pragma unroll
    for (int j = 0; j < 4; j++) {
        if (j >= cnt) break;
        pos[j] = atomicAdd(&g_cur[d[j]], 1);
    }
#pragma unroll
    for (int j = 0; j < 4; j++) {
        if (j >= cnt) break;
        g_col[pos[j]] = s[j];
    }
}

// ---------------- fused bconv + LN1->A1 image ---------------------------------
#define BCONV_TOT (128*128 + 128*256 + 256*128)
#define BCONV_BLK ((BCONV_TOT + 255) / 256)
__global__ void bconv_ln_kernel(const float* __restrict__ W,
                                const float* __restrict__ w1,
                                const float* __restrict__ w2,
                                const float* __restrict__ in,
                                const float* __restrict__ gg,
                                const float* __restrict__ bb, int n) {
    if (blockIdx.x < BCONV_BLK) {
        int idx = blockIdx.x * 256 + threadIdx.x;
        const float* src; char* dst; int K, Nn;
        if (idx < 128 * 128)              { src = W;  dst = g_B1; K = 128; Nn = 128; }
        else if (idx < 128*128 + 128*256) { idx -= 128*128; src = w1; dst = g_B2; K = 128; Nn = 256; }
        else if (idx < BCONV_TOT)         { idx -= 128*128 + 128*256; src = w2; dst = g_B3; K = 256; Nn = 128; }
        else return;
        int k = idx / Nn, nn = idx % Nn;
        float v = src[(size_t)k * Nn + nn];
        __nv_bfloat16 h = __float2bfloat16(v);
        __nv_bfloat16 l = __float2bfloat16(v - __bfloat162float(h));
        int nch = K >> 6, ch = k >> 6, kk = k & 63;
        size_t tile = (size_t)Nn * 128;
        uint32_t off = SWZ(nn * 128 + kk * 2);
        *(__nv_bfloat16*)(dst + (size_t)(0 * nch + ch) * tile + off) = h;
        *(__nv_bfloat16*)(dst + (size_t)(1 * nch + ch) * tile + off) = l;
        return;
    }
    int row  = (blockIdx.x - BCONV_BLK) * 8 + (threadIdx.x >> 5);
    int lane = threadIdx.x & 31;
    if (row >= n) return;
    const float4 v = *(const float4*)&in[(size_t)row * DIN + lane * 4];
    float s  = warpSum(v.x + v.y + v.z + v.w);
    float sq = warpSum(v.x * v.x + v.y * v.y + v.z * v.z + v.w * v.w);
    float m = s * (1.f / DIN);
    float inv = rsqrtf(sq * (1.f / DIN) - m * m + EPSV);
    const float4 g = *(const float4*)&gg[lane * 4];
    const float4 b = *(const float4*)&bb[lane * 4];
    float4 o;
    o.x = (v.x - m) * inv * g.x + b.x;
    o.y = (v.y - m) * inv * g.y + b.y;
    o.z = (v.z - m) * inv * g.z + b.z;
    o.w = (v.w - m) * inv * g.w + b.w;
    int mtile = row >> 7, r = row & 127;
    int col0 = lane * 4, ch = col0 >> 6, kk = col0 & 63;
    uint32_t off = SWZ(r * 128 + kk * 2);
    char* base = g_A1 + (size_t)mtile * (2 * 2 * 16384);
    split_store8(base, (size_t)(0 * 2 + ch) * 16384, (size_t)(1 * 2 + ch) * 16384, off, o);
}

// ---------------- warp-MMA GEMM, 64x128 block tile, 2 CTAs/SM -----------------
template <int NTOT, int NCH, int EPI>
__global__ void __launch_bounds__(256, 2)
mma_gemm(const char* __restrict__ Aimg, const char* __restrict__ Bimg,
         const float* __restrict__ bias, const float* __restrict__ resid,
         float* __restrict__ outF, char* __restrict__ outImg,
         const float* __restrict__ attS, const float* __restrict__ attD, int M) {
    extern __shared__ char smem[];
    const uint32_t sb = smem_u32(smem);
    const int tid = threadIdx.x, wid = tid >> 5, lane = tid & 31;
    const int mblk = blockIdx.x, nb = blockIdx.y;
    const int mtile128 = mblk >> 1, mhalf = mblk & 1;
    const int wm = wid & 1, wn = wid >> 1;

    const char* Ab = Aimg + (size_t)mtile128 * (2 * NCH * 16384) + (size_t)mhalf * 8192;

    int rowTA[2], rowTB[2];
#pragma unroll
    for (int mf = 0; mf < 2; mf++)
        rowTA[mf] = (wm * 32 + mf * 16 + (lane & 15)) * 128 + (lane >> 4) * 16;
#pragma unroll
    for (int nfg = 0; nfg < 2; nfg++)
        rowTB[nfg] = (wn * 32 + nfg * 16 + (lane >> 4) * 8 + (lane & 7)) * 128
                   + ((lane >> 3) & 1) * 16;

    float acc[2][4][4];
#pragma unroll
    for (int i = 0; i < 2; i++)
#pragma unroll
        for (int j = 0; j < 4; j++)
#pragma unroll
            for (int q = 0; q < 4; q++) acc[i][j][q] = 0.f;

    auto stage = [&](int c, int bufIdx) {
        const char* aSrc[2] = {
            Ab + (size_t)(0 * NCH + c) * 16384,
            Ab + (size_t)(1 * NCH + c) * 16384
        };
        const char* bSrc[2] = {
            Bimg + (size_t)(0 * NCH + c) * ((size_t)NTOT * 128) + (size_t)nb * 16384,
            Bimg + (size_t)(1 * NCH + c) * ((size_t)NTOT * 128) + (size_t)nb * 16384
        };
        uint32_t dbase = sb + bufIdx * 49152;
#pragma unroll
        for (int sel = 0; sel < 2; sel++) {
#pragma unroll
            for (int i = 0; i < 2; i++) {
                int ofs = (tid + 256 * i) * 16;
                cpasync16(dbase + sel * 8192 + ofs, aSrc[sel] + ofs);
            }
#pragma unroll
            for (int i = 0; i < 4; i++) {
                int ofs = (tid + 256 * i) * 16;
                cpasync16(dbase + 16384 + sel * 16384 + ofs, bSrc[sel] + ofs);
            }
        }
        asm volatile("cp.async.commit_group;" ::: "memory");
    };

    stage(0, 0);
    int buf = 0;
    for (int c = 0; c < NCH; c++) {
        if (c + 1 < NCH) {
            stage(c + 1, buf ^ 1);
            asm volatile("cp.async.wait_group 1;" ::: "memory");
        } else {
            asm volatile("cp.async.wait_group 0;" ::: "memory");
        }
        __syncthreads();

        const uint32_t bbase = sb + buf * 49152;
#pragma unroll
        for (int kk = 0; kk < 4; kk++) {
            uint32_t ah[2][4], al[2][4];
#pragma unroll
            for (int mf = 0; mf < 2; mf++) {
                uint32_t off = SWZ(rowTA[mf] + kk * 32);
                ldsm4(ah[mf], bbase + off);
                ldsm4(al[mf], bbase + 8192 + off);
            }
#pragma unroll
            for (int nfg = 0; nfg < 2; nfg++) {
                uint32_t bh[4], bl[4];
                uint32_t off = SWZ(rowTB[nfg] + kk * 32);
                ldsm4(bh, bbase + 16384 + off);
                ldsm4(bl, bbase + 32768 + off);
#pragma unroll
                for (int mf = 0; mf < 2; mf++) {
                    mma16816(acc[mf][2 * nfg],     ah[mf], bh);
                    mma16816(acc[mf][2 * nfg],     al[mf], bh);
                    mma16816(acc[mf][2 * nfg],     ah[mf], bl);
                    mma16816(acc[mf][2 * nfg + 1], ah[mf], bh + 2);
                    mma16816(acc[mf][2 * nfg + 1], al[mf], bh + 2);
                    mma16816(acc[mf][2 * nfg + 1], ah[mf], bl + 2);
                }
            }
        }
        __syncthreads();
        buf ^= 1;
    }

    // ---------------- epilogue ----------------
#pragma unroll
    for (int mf = 0; mf < 2; mf++) {
        const int rl0 = wm * 32 + mf * 16 + (lane >> 2);   // local row 0..63
        const int m0 = mblk * 64 + rl0;
        const int m1 = m0 + 8;
        float ps0 = 0.f, pd0 = 0.f, ps1 = 0.f, pd1 = 0.f;
#pragma unroll
        for (int nfr = 0; nfr < 4; nfr++) {
            const int col = nb * 128 + wn * 32 + nfr * 8 + (lane & 3) * 2;
            float* cc = acc[mf][nfr];
            if (EPI == 0) {
                const float as0 = attS[col], as1 = attS[col + 1];
                const float ad0 = attD[col], ad1 = attD[col + 1];
                ps0 += cc[0] * as0 + cc[1] * as1;
                pd0 += cc[0] * ad0 + cc[1] * ad1;
                ps1 += cc[2] * as0 + cc[3] * as1;
                pd1 += cc[2] * ad0 + cc[3] * ad1;
                __half2 v0 = __floats2half2_rn(cc[0], cc[1]);
                __half2 v1 = __floats2half2_rn(cc[2], cc[3]);
                if (m0 < M) *(__half2*)&g_xhh[(size_t)m0 * DIN + col] = v0;
                if (m1 < M) *(__half2*)&g_xhh[(size_t)m1 * DIN + col] = v1;
            } else if (EPI == 1) {
                char* img = outImg + (size_t)mtile128 * (2 * 4 * 16384);
                const int ir0 = mhalf * 64 + rl0;           // image row 0..127
                const float b0 = bias[col], b1 = bias[col + 1];
                const int ch = col >> 6, kk = col & 63;
                const size_t hiOff = (size_t)(0 * 4 + ch) * 16384;
                const size_t loOff = (size_t)(1 * 4 + ch) * 16384;
                if (m0 < M) {
                    uint32_t hp, lp;
                    split2(geluf(cc[0] + b0), geluf(cc[1] + b1), hp, lp);
                    uint32_t off = SWZ(ir0 * 128 + kk * 2);
                    *(uint32_t*)(img + hiOff + off) = hp;
                    *(uint32_t*)(img + loOff + off) = lp;
                }
                if (m1 < M) {
                    uint32_t hp, lp;
                    split2(geluf(cc[2] + b0), geluf(cc[3] + b1), hp, lp);
                    uint32_t off = SWZ((ir0 + 8) * 128 + kk * 2);
                    *(uint32_t*)(img + hiOff + off) = hp;
                    *(uint32_t*)(img + loOff + off) = lp;
                }
            } else {
                const float b0 = bias[col], b1 = bias[col + 1];
                if (m0 < M) {
                    const float2 rr = *(const float2*)&resid[(size_t)m0 * NTOT + col];
                    *(float2*)&outF[(size_t)m0 * NTOT + col] =
                        make_float2(cc[0] + b0 + rr.x, cc[1] + b1 + rr.y);
                }
                if (m1 < M) {
                    const float2 rr = *(const float2*)&resid[(size_t)m1 * NTOT + col];
                    *(float2*)&outF[(size_t)m1 * NTOT + col] =
                        make_float2(cc[2] + b0 + rr.x, cc[3] + b1 + rr.y);
                }
            }
        }
        if (EPI == 0) {
#pragma unroll
            for (int o = 1; o <= 2; o <<= 1) {
                ps0 += __shfl_xor_sync(0xffffffffu, ps0, o);
                pd0 += __shfl_xor_sync(0xffffffffu, pd0, o);
                ps1 += __shfl_xor_sync(0xffffffffu, ps1, o);
                pd1 += __shfl_xor_sync(0xffffffffu, pd1, o);
            }
            if ((lane & 3) == 0) {
                if (m0 < M) {
                    g_asrc[m0 * NHEAD + wn] = ps0;
                    g_adst[m0 * NHEAD + wn] = pd0;
                }
                if (m1 < M) {
                    g_asrc[m1 * NHEAD + wn] = ps1;
                    g_adst[m1 * NHEAD + wn] = pd1;
                }
            }
        }
    }
}

// ---- fused gather aggregation: softmax + weighted sum + +gat_b + resid + LN2 -
__global__ void csr_agg_kernel(const float* __restrict__ x,
                               const float* __restrict__ gat_b,
                               const float* __restrict__ g2,
                               const float* __restrict__ b2, int n, int Et) {
    int row  = blockIdx.x * 8 + (threadIdx.x >> 5);
    int lane = threadIdx.x & 31;
    if (row >= n) return;
    const int h = lane >> 3;
    const float adst_h = g_adst[row * NHEAD + h];
    const int p0 = g_rowp[row];
    const int p1 = (row == n - 1) ? Et : g_rowp[row + 1];

    float4 acc = make_float4(0.f, 0.f, 0.f, 0.f);
    float den = 0.f;
    for (int p = p0; p < p1; p++) {
        int s = g_col[p];
        float ex = expf(lrelu(g_asrc[s * NHEAD + h] + adst_h));
        den += ex;
        const uint2 raw = *(const uint2*)&g_xhh[(size_t)s * DIN + lane * 4];
        const float2 f0 = __half22float2(*(const __half2*)&raw.x);
        const float2 f1 = __half22float2(*(const __half2*)&raw.y);
        acc.x += f0.x * ex; acc.y += f0.y * ex;
        acc.z += f1.x * ex; acc.w += f1.y * ex;
    }
    float inv = 1.f / den;
    const float4 xv = *(const float4*)&x[(size_t)row * DIN + lane * 4];
    const float4 gb = *(const float4*)&gat_b[lane * 4];
    float4 h2;
    h2.x = acc.x * inv + gb.x + xv.x;
    h2.y = acc.y * inv + gb.y + xv.y;
    h2.z = acc.z * inv + gb.z + xv.z;
    h2.w = acc.w * inv + gb.w + xv.w;
    *(float4*)&g_h2[(size_t)row * DIN + lane * 4] = h2;

    float s  = warpSum(h2.x + h2.y + h2.z + h2.w);
    float sq = warpSum(h2.x * h2.x + h2.y * h2.y + h2.z * h2.z + h2.w * h2.w);
    float m = s * (1.f / DIN);
    float rin = rsqrtf(sq * (1.f / DIN) - m * m + EPSV);
    const float4 g = *(const float4*)&g2[lane * 4];
    const float4 b = *(const float4*)&b2[lane * 4];
    float4 o;
    o.x = (h2.x - m) * rin * g.x + b.x;
    o.y = (h2.y - m) * rin * g.y + b.y;
    o.z = (h2.z - m) * rin * g.z + b.z;
    o.w = (h2.w - m) * rin * g.w + b.w;
    int mtile = row >> 7, r = row & 127;
    int col0 = lane * 4, ch = col0 >> 6, kk = col0 & 63;
    uint32_t off = SWZ(r * 128 + kk * 2);
    char* base = g_A2 + (size_t)mtile * (2 * 2 * 16384);
    split_store8(base, (size_t)(0 * 2 + ch) * 16384, (size_t)(1 * 2 + ch) * 16384, off, o);
}

// ---------------- launch ------------------------------------------------------
extern "C" void kernel_launch(void* const* d_in, const int* in_sizes, int n_in,
                              void* d_out, int out_size) {
    const float* x     = (const float*)d_in[0];
    const void*  ei    = d_in[1];
    const float* ln1_g = (const float*)d_in[2];
    const float* ln1_b = (const float*)d_in[3];
    const float* W     = (const float*)d_in[4];
    const float* att_s = (const float*)d_in[5];
    const float* att_d = (const float*)d_in[6];
    const float* gat_b = (const float*)d_in[7];
    const float* ln2_g = (const float*)d_in[8];
    const float* ln2_b = (const float*)d_in[9];
    const float* w1    = (const float*)d_in[10];
    const float* b1    = (const float*)d_in[11];
    const float* w2    = (const float*)d_in[12];
    const float* b2    = (const float*)d_in[13];
    float*       out   = (float*)d_out;

    const int n      = in_sizes[0] / DIN;
    const int E      = in_sizes[1] / 2;
    const int Et     = E + n;
    const int mtiles = (n + 127) / 128;
    const int mblks  = 2 * mtiles;
    const int nparts = (n + 1023) / 1024;

    float* ph2;  cudaGetSymbolAddress((void**)&ph2, g_h2);
    char*  pA1;  cudaGetSymbolAddress((void**)&pA1, g_A1);
    char*  pA2;  cudaGetSymbolAddress((void**)&pA2, g_A2);
    char*  pA3;  cudaGetSymbolAddress((void**)&pA3, g_A3);
    char*  pB1;  cudaGetSymbolAddress((void**)&pB1, g_B1);
    char*  pB2;  cudaGetSymbolAddress((void**)&pB2, g_B2);
    char*  pB3;  cudaGetSymbolAddress((void**)&pB3, g_B3);
    int*   pcnt; cudaGetSymbolAddress((void**)&pcnt, g_cnt);

    const int SMEM = 98304;   // double-buffered 2 x 48KB -> 2 CTAs/SM
    cudaFuncSetAttribute(mma_gemm<128, 2, 0>, cudaFuncAttributeMaxDynamicSharedMemorySize, SMEM);
    cudaFuncSetAttribute(mma_gemm<256, 2, 1>, cudaFuncAttributeMaxDynamicSharedMemorySize, SMEM);
    cudaFuncSetAttribute(mma_gemm<128, 4, 2>, cudaFuncAttributeMaxDynamicSharedMemorySize, SMEM);

    // one-time resources (host-side only; no device memory)
    static cudaStream_t s2 = nullptr;
    static cudaEvent_t evFork = nullptr, evCsr = nullptr;
    if (!s2) {
        cudaStreamCreateWithFlags(&s2, cudaStreamNonBlocking);
        cudaEventCreateWithFlags(&evFork, cudaEventDisableTiming);
        cudaEventCreateWithFlags(&evCsr, cudaEventDisableTiming);
    }

    // fork: CSR build on side stream (independent of LN/bconv/GEMM1 path)
    cudaEventRecord(evFork, 0);
    cudaStreamWaitEvent(s2, evFork, 0);
    cudaMemsetAsync(pcnt, 0, (size_t)n * sizeof(int), s2);
    detect_kernel<<<1, 256, 0, s2>>>((const int*)ei, E);
    count_kernel<<<(Et + 1023) / 1024, 256, 0, s2>>>(ei, E, Et);
    scan_kernel<<<nparts, 256, 0, s2>>>(n);
    scatter_kernel<<<(Et + 1023) / 1024, 256, 0, s2>>>(Et);
    cudaEventRecord(evCsr, s2);

    // main path
    bconv_ln_kernel<<<BCONV_BLK + (n + 7) / 8, 256>>>(W, w1, w2, x, ln1_g, ln1_b, n);
    mma_gemm<128, 2, 0><<<dim3(mblks, 1), 256, SMEM>>>(
        pA1, pB1, nullptr, nullptr, nullptr, nullptr, att_s, att_d, n);

    // join: csr_agg needs both CSR and GEMM1 outputs
    cudaStreamWaitEvent(0, evCsr, 0);
    csr_agg_kernel<<<(n + 7) / 8, 256>>>(x, gat_b, ln2_g, ln2_b, n, Et);
    mma_gemm<256, 2, 1><<<dim3(mblks, 2), 256, SMEM>>>(
        pA2, pB2, b1, nullptr, nullptr, pA3, nullptr, nullptr, n);
    mma_gemm<128, 4, 2><<<dim3(mblks, 1), 256, SMEM>>>(
        pA3, pB3, b2, ph2, out, nullptr, nullptr, nullptr, n);
}

// round 15
// speedup vs baseline: 1.1140x; 1.1140x over previous
#include <cuda_runtime.h>
#include <cuda_bf16.h>
#include <cuda_fp16.h>
#include <math.h>
#include <float.h>
#include <stdint.h>

#define DIN   128
#define NHEAD 4
#define EPSV  1e-5f
#define SLOPE 0.2f
#define MAXN  50000
#define MAXE  800000
#define MAXT  392            // max M tiles of 128

// ---------------- scratch (static device globals; no allocation) ------------
__device__ __half g_xhh[(size_t)MAXN * DIN];            // h @ W (fp16 messages)
__device__ float  g_h2 [(size_t)MAXN * DIN];            // gat out + residual
__device__ float  g_asrc[(size_t)MAXN * NHEAD];
__device__ float  g_adst[(size_t)MAXN * NHEAD];
__device__ int    g_src [MAXE + MAXN];
__device__ int    g_dst [MAXE + MAXN];
__device__ int    g_col [MAXE + MAXN];                  // CSR: src per slot
__device__ int    g_cnt [MAXN];
__device__ int    g_rowp[MAXN + 1];
__device__ int    g_cur [MAXN];
__device__ int    g_is64;

// A-operand images, pre-swizzled SMEM tile layout:
// [mtile][sel(hi=0,lo=1)][chunk][128 rows x 128 bytes, SW128]   (chunk = 64 k-vals)
__device__ __align__(16) char g_A1[(size_t)MAXT * 2 * 2 * 16384];  // LN1(x)  bf16 hi/lo, K=128
__device__ __align__(16) char g_A2[(size_t)MAXT * 2 * 2 * 16384];  // LN2(h2) fp16 hi/lo, K=128
__device__ __align__(16) char g_A3[(size_t)MAXT * 2 * 4 * 16384];  // ffn1    fp16 hi/lo, K=256
// B images: W bf16 hi/lo [sel][ch][...]; w1/w2 fp16 single [ch][N rows x 128B]
__device__ __align__(16) char g_B1[2 * 2 * 128 * 128];
__device__ __align__(16) char g_B2[2 * 256 * 128];
__device__ __align__(16) char g_B3[4 * 128 * 128];

// ---------------- helpers ------------------------------------------------------
#define SWZ(o) ((uint32_t)(o) ^ ((((uint32_t)(o)) >> 3) & 0x70u))

__device__ __forceinline__ uint32_t smem_u32(const void* p) {
    uint32_t a;
    asm("{ .reg .u64 t; cvta.to.shared.u64 t, %1; cvt.u32.u64 %0, t; }" : "=r"(a) : "l"(p));
    return a;
}
__device__ __forceinline__ void ldsm4(uint32_t* r, uint32_t addr) {
    asm volatile("ldmatrix.sync.aligned.m8n8.x4.shared.b16 {%0,%1,%2,%3}, [%4];"
                 : "=r"(r[0]), "=r"(r[1]), "=r"(r[2]), "=r"(r[3]) : "r"(addr));
}
__device__ __forceinline__ void mma16816(float* c, const uint32_t* a, const uint32_t* b) {
    asm volatile("mma.sync.aligned.m16n8k16.row.col.f32.bf16.bf16.f32 "
                 "{%0,%1,%2,%3}, {%4,%5,%6,%7}, {%8,%9}, {%0,%1,%2,%3};"
                 : "+f"(c[0]), "+f"(c[1]), "+f"(c[2]), "+f"(c[3])
                 : "r"(a[0]), "r"(a[1]), "r"(a[2]), "r"(a[3]), "r"(b[0]), "r"(b[1]));
}
__device__ __forceinline__ void mma16816h(float* c, const uint32_t* a, const uint32_t* b) {
    asm volatile("mma.sync.aligned.m16n8k16.row.col.f32.f16.f16.f32 "
                 "{%0,%1,%2,%3}, {%4,%5,%6,%7}, {%8,%9}, {%0,%1,%2,%3};"
                 : "+f"(c[0]), "+f"(c[1]), "+f"(c[2]), "+f"(c[3])
                 : "r"(a[0]), "r"(a[1]), "r"(a[2]), "r"(a[3]), "r"(b[0]), "r"(b[1]));
}
__device__ __forceinline__ void cpasync16(uint32_t dst, const void* src) {
    asm volatile("cp.async.cg.shared.global [%0], [%1], 16;" :: "r"(dst), "l"(src) : "memory");
}
__device__ __forceinline__ float warpSum(float v) {
#pragma unroll
    for (int o = 16; o; o >>= 1) v += __shfl_xor_sync(0xffffffffu, v, o);
    return v;
}
__device__ __forceinline__ float geluf(float v) {
    return 0.5f * v * (1.f + erff(v * 0.70710678118654752440f));
}
__device__ __forceinline__ float lrelu(float v) { return v > 0.f ? v : SLOPE * v; }

// bf16 hi/lo split (pairs)
__device__ __forceinline__ void split2(float v0, float v1, uint32_t& hi, uint32_t& lo) {
    __nv_bfloat16 h0 = __float2bfloat16(v0), h1 = __float2bfloat16(v1);
    __nv_bfloat16 l0 = __float2bfloat16(v0 - __bfloat162float(h0));
    __nv_bfloat16 l1 = __float2bfloat16(v1 - __bfloat162float(h1));
    __nv_bfloat162 hp; hp.x = h0; hp.y = h1;
    __nv_bfloat162 lp; lp.x = l0; lp.y = l1;
    hi = *(uint32_t*)&hp; lo = *(uint32_t*)&lp;
}
// fp16 hi/lo split (pairs)
__device__ __forceinline__ void split2h(float v0, float v1, uint32_t& hi, uint32_t& lo) {
    __half h0 = __float2half_rn(v0), h1 = __float2half_rn(v1);
    __half l0 = __float2half_rn(v0 - __half2float(h0));
    __half l1 = __float2half_rn(v1 - __half2float(h1));
    __half2 hp; hp.x = h0; hp.y = h1;
    __half2 lp; lp.x = l0; lp.y = l1;
    hi = *(uint32_t*)&hp; lo = *(uint32_t*)&lp;
}
__device__ __forceinline__ void split_store8(char* base, size_t hiOff, size_t loOff,
                                             uint32_t off, float4 o) {
    uint32_t h0, l0, h1, l1;
    split2(o.x, o.y, h0, l0);
    split2(o.z, o.w, h1, l1);
    *(uint32_t*)(base + hiOff + off)     = h0;
    *(uint32_t*)(base + hiOff + off + 4) = h1;
    *(uint32_t*)(base + loOff + off)     = l0;
    *(uint32_t*)(base + loOff + off + 4) = l1;
}
__device__ __forceinline__ void split_store8h(char* base, size_t hiOff, size_t loOff,
                                              uint32_t off, float4 o) {
    uint32_t h0, l0, h1, l1;
    split2h(o.x, o.y, h0, l0);
    split2h(o.z, o.w, h1, l1);
    *(uint32_t*)(base + hiOff + off)     = h0;
    *(uint32_t*)(base + hiOff + off + 4) = h1;
    *(uint32_t*)(base + loOff + off)     = l0;
    *(uint32_t*)(base + loOff + off + 4) = l1;
}

// ---------------- detect dtype (1 block; g_cnt zeroed by memsetAsync) ---------
__global__ void detect_kernel(const int* __restrict__ ei32, int E) {
    __shared__ int any;
    if (threadIdx.x == 0) any = 0;
    __syncthreads();
    int samples = min(E, 4096);
    int local = 0;
    for (int k = threadIdx.x; k < samples; k += blockDim.x)
        if (ei32[2 * k + 1] != 0) local = 1;
    if (local) atomicOr(&any, 1);
    __syncthreads();
    if (threadIdx.x == 0) g_is64 = any ? 0 : 1;
}

__global__ void count_kernel(const void* __restrict__ ei, int E, int Et) {
    int e = blockIdx.x * blockDim.x + threadIdx.x;
    if (e >= Et) return;
    int s, d;
    if (e < E) {
        if (g_is64) {
            const long long* p = (const long long*)ei;
            s = (int)p[e]; d = (int)p[(size_t)E + e];
        } else {
            const int* p = (const int*)ei;
            s = p[e]; d = p[E + e];
        }
    } else { s = d = e - E; }
    g_src[e] = s; g_dst[e] = d;
    atomicAdd(&g_cnt[d], 1);
}

// merged scan: each block self-computes its chunk base
__global__ void scan_kernel(int n) {
    __shared__ int wsum[8];
    __shared__ int red[8];
    __shared__ int chunkBase;
    int b = blockIdx.x, tid = threadIdx.x;
    int lane = tid & 31, wid = tid >> 5;
    {
        int pre = b * 1024;
        int s = 0;
        for (int i = tid; i < pre; i += 256) s += g_cnt[i];
#pragma unroll
        for (int o = 16; o; o >>= 1) s += __shfl_xor_sync(0xffffffffu, s, o);
        if (lane == 0) red[wid] = s;
        __syncthreads();
        if (tid == 0) {
            int t = 0;
#pragma unroll
            for (int w = 0; w < 8; w++) t += red[w];
            chunkBase = t;
        }
    }
    int i0 = b * 1024 + tid * 4;
    int v[4];
#pragma unroll
    for (int j = 0; j < 4; j++) v[j] = (i0 + j < n) ? g_cnt[i0 + j] : 0;
    int tsum = v[0] + v[1] + v[2] + v[3];
    int incl = tsum;
#pragma unroll
    for (int o = 1; o < 32; o <<= 1) {
        int t = __shfl_up_sync(0xffffffffu, incl, o);
        if (lane >= o) incl += t;
    }
    if (lane == 31) wsum[wid] = incl;
    __syncthreads();
    if (tid == 0) {
        int s = 0;
#pragma unroll
        for (int w = 0; w < 8; w++) { int t = wsum[w]; wsum[w] = s; s += t; }
    }
    __syncthreads();
    int run = chunkBase + wsum[wid] + incl - tsum;
#pragma unroll
    for (int j = 0; j < 4; j++) {
        if (i0 + j < n) { g_rowp[i0 + j] = run; g_cur[i0 + j] = run; }
        run += v[j];
    }
}

__global__ void scatter_kernel(int Et) {
    int e = blockIdx.x * blockDim.x + threadIdx.x;
    if (e >= Et) return;
    int d = g_dst[e];
    int pos = atomicAdd(&g_cur[d], 1);
    g_col[pos] = g_src[e];
}

// ---------------- fused bconv + LN1->A1 image ---------------------------------
// W -> bf16 hi/lo (g_B1); w1/w2 -> fp16 single (g_B2/g_B3)
#define BCONV_TOT (128*128 + 128*256 + 256*128)
#define BCONV_BLK ((BCONV_TOT + 255) / 256)
__global__ void bconv_ln_kernel(const float* __restrict__ W,
                                const float* __restrict__ w1,
                                const float* __restrict__ w2,
                                const float* __restrict__ in,
                                const float* __restrict__ gg,
                                const float* __restrict__ bb, int n) {
    if (blockIdx.x < BCONV_BLK) {
        int idx = blockIdx.x * 256 + threadIdx.x;
        if (idx < 128 * 128) {
            // W: bf16 hi/lo
            int k = idx / 128, nn = idx % 128;
            float v = W[(size_t)k * 128 + nn];
            __nv_bfloat16 h = __float2bfloat16(v);
            __nv_bfloat16 l = __float2bfloat16(v - __bfloat162float(h));
            int ch = k >> 6, kk = k & 63;
            uint32_t off = SWZ(nn * 128 + kk * 2);
            *(__nv_bfloat16*)(g_B1 + (size_t)(0 * 2 + ch) * 16384 + off) = h;
            *(__nv_bfloat16*)(g_B1 + (size_t)(1 * 2 + ch) * 16384 + off) = l;
        } else if (idx < 128*128 + 128*256) {
            // w1: fp16 single, [2 ch][256 rows x 128B]
            idx -= 128 * 128;
            int k = idx / 256, nn = idx % 256;
            float v = w1[(size_t)k * 256 + nn];
            int ch = k >> 6, kk = k & 63;
            uint32_t off = SWZ(nn * 128 + kk * 2);
            *(__half*)(g_B2 + (size_t)ch * (256 * 128) + off) = __float2half_rn(v);
        } else if (idx < BCONV_TOT) {
            // w2: fp16 single, [4 ch][128 rows x 128B]
            idx -= 128*128 + 128*256;
            int k = idx / 128, nn = idx % 128;
            float v = w2[(size_t)k * 128 + nn];
            int ch = k >> 6, kk = k & 63;
            uint32_t off = SWZ(nn * 128 + kk * 2);
            *(__half*)(g_B3 + (size_t)ch * (128 * 128) + off) = __float2half_rn(v);
        }
        return;
    }
    int row  = (blockIdx.x - BCONV_BLK) * 8 + (threadIdx.x >> 5);
    int lane = threadIdx.x & 31;
    if (row >= n) return;
    const float4 v = *(const float4*)&in[(size_t)row * DIN + lane * 4];
    float s  = warpSum(v.x + v.y + v.z + v.w);
    float sq = warpSum(v.x * v.x + v.y * v.y + v.z * v.z + v.w * v.w);
    float m = s * (1.f / DIN);
    float inv = rsqrtf(sq * (1.f / DIN) - m * m + EPSV);
    const float4 g = *(const float4*)&gg[lane * 4];
    const float4 b = *(const float4*)&bb[lane * 4];
    float4 o;
    o.x = (v.x - m) * inv * g.x + b.x;
    o.y = (v.y - m) * inv * g.y + b.y;
    o.z = (v.z - m) * inv * g.z + b.z;
    o.w = (v.w - m) * inv * g.w + b.w;
    int mtile = row >> 7, r = row & 127;
    int col0 = lane * 4, ch = col0 >> 6, kk = col0 & 63;
    uint32_t off = SWZ(r * 128 + kk * 2);
    char* base = g_A1 + (size_t)mtile * (2 * 2 * 16384);
    split_store8(base, (size_t)(0 * 2 + ch) * 16384, (size_t)(1 * 2 + ch) * 16384, off, o);
}

// ---------------- warp-MMA GEMM, 64x128 block tile, 2 CTAs/SM -----------------
// F16=0: bf16, A hi/lo x B hi/lo, 3-MMA compensation (GEMM1).
// F16=1: fp16, A hi/lo x B single, 2-MMA compensation (GEMM2/GEMM3).
// EPI 0: fp16 xh table + attention logits. EPI 1: gelu -> A3 fp16 image. EPI 2: +bias+resid.
template <int NTOT, int NCH, int EPI, int F16>
__global__ void __launch_bounds__(256, 2)
mma_gemm(const char* __restrict__ Aimg, const char* __restrict__ Bimg,
         const float* __restrict__ bias, const float* __restrict__ resid,
         float* __restrict__ outF, char* __restrict__ outImg,
         const float* __restrict__ attS, const float* __restrict__ attD, int M) {
    extern __shared__ char smem[];
    const uint32_t sb = smem_u32(smem);
    const int tid = threadIdx.x, wid = tid >> 5, lane = tid & 31;
    const int mblk = blockIdx.x, nb = blockIdx.y;
    const int mtile128 = mblk >> 1, mhalf = mblk & 1;
    const int wm = wid & 1, wn = wid >> 1;
    constexpr int BUFS = F16 ? 32768 : 49152;   // stage bytes

    const char* Ab = Aimg + (size_t)mtile128 * (2 * NCH * 16384) + (size_t)mhalf * 8192;

    int rowTA[2], rowTB[2];
#pragma unroll
    for (int mf = 0; mf < 2; mf++)
        rowTA[mf] = (wm * 32 + mf * 16 + (lane & 15)) * 128 + (lane >> 4) * 16;
#pragma unroll
    for (int nfg = 0; nfg < 2; nfg++)
        rowTB[nfg] = (wn * 32 + nfg * 16 + (lane >> 4) * 8 + (lane & 7)) * 128
                   + ((lane >> 3) & 1) * 16;

    float acc[2][4][4];
#pragma unroll
    for (int i = 0; i < 2; i++)
#pragma unroll
        for (int j = 0; j < 4; j++)
#pragma unroll
            for (int q = 0; q < 4; q++) acc[i][j][q] = 0.f;

    // stage layout: Ah[0,8K) Al[8K,16K) B(h)[16K,32K) (+Bl[32K,48K) if !F16)
    auto stage = [&](int c, int bufIdx) {
        const char* aSrc[2] = {
            Ab + (size_t)(0 * NCH + c) * 16384,
            Ab + (size_t)(1 * NCH + c) * 16384
        };
        uint32_t dbase = sb + bufIdx * BUFS;
#pragma unroll
        for (int sel = 0; sel < 2; sel++) {
#pragma unroll
            for (int i = 0; i < 2; i++) {
                int ofs = (tid + 256 * i) * 16;
                cpasync16(dbase + sel * 8192 + ofs, aSrc[sel] + ofs);
            }
        }
        if (F16) {
            const char* bSrc = Bimg + (size_t)c * ((size_t)NTOT * 128) + (size_t)nb * 16384;
#pragma unroll
            for (int i = 0; i < 4; i++) {
                int ofs = (tid + 256 * i) * 16;
                cpasync16(dbase + 16384 + ofs, bSrc + ofs);
            }
        } else {
#pragma unroll
            for (int sel = 0; sel < 2; sel++) {
                const char* bSrc = Bimg + (size_t)(sel * NCH + c) * ((size_t)NTOT * 128)
                                 + (size_t)nb * 16384;
#pragma unroll
                for (int i = 0; i < 4; i++) {
                    int ofs = (tid + 256 * i) * 16;
                    cpasync16(dbase + 16384 + sel * 16384 + ofs, bSrc + ofs);
                }
            }
        }
        asm volatile("cp.async.commit_group;" ::: "memory");
    };

    stage(0, 0);
    int buf = 0;
    for (int c = 0; c < NCH; c++) {
        if (c + 1 < NCH) {
            stage(c + 1, buf ^ 1);
            asm volatile("cp.async.wait_group 1;" ::: "memory");
        } else {
            asm volatile("cp.async.wait_group 0;" ::: "memory");
        }
        __syncthreads();

        const uint32_t bbase = sb + buf * BUFS;
#pragma unroll
        for (int kk = 0; kk < 4; kk++) {
            uint32_t ah[2][4], al[2][4];
#pragma unroll
            for (int mf = 0; mf < 2; mf++) {
                uint32_t off = SWZ(rowTA[mf] + kk * 32);
                ldsm4(ah[mf], bbase + off);
                ldsm4(al[mf], bbase + 8192 + off);
            }
#pragma unroll
            for (int nfg = 0; nfg < 2; nfg++) {
                uint32_t off = SWZ(rowTB[nfg] + kk * 32);
                if (F16) {
                    uint32_t bq[4];
                    ldsm4(bq, bbase + 16384 + off);
#pragma unroll
                    for (int mf = 0; mf < 2; mf++) {
                        mma16816h(acc[mf][2 * nfg],     ah[mf], bq);
                        mma16816h(acc[mf][2 * nfg],     al[mf], bq);
                        mma16816h(acc[mf][2 * nfg + 1], ah[mf], bq + 2);
                        mma16816h(acc[mf][2 * nfg + 1], al[mf], bq + 2);
                    }
                } else {
                    uint32_t bh[4], bl[4];
                    ldsm4(bh, bbase + 16384 + off);
                    ldsm4(bl, bbase + 32768 + off);
#pragma unroll
                    for (int mf = 0; mf < 2; mf++) {
                        mma16816(acc[mf][2 * nfg],     ah[mf], bh);
                        mma16816(acc[mf][2 * nfg],     al[mf], bh);
                        mma16816(acc[mf][2 * nfg],     ah[mf], bl);
                        mma16816(acc[mf][2 * nfg + 1], ah[mf], bh + 2);
                        mma16816(acc[mf][2 * nfg + 1], al[mf], bh + 2);
                        mma16816(acc[mf][2 * nfg + 1], ah[mf], bl + 2);
                    }
                }
            }
        }
        __syncthreads();
        buf ^= 1;
    }

    // ---------------- epilogue ----------------
#pragma unroll
    for (int mf = 0; mf < 2; mf++) {
        const int rl0 = wm * 32 + mf * 16 + (lane >> 2);   // local row 0..63
        const int m0 = mblk * 64 + rl0;
        const int m1 = m0 + 8;
        float ps0 = 0.f, pd0 = 0.f, ps1 = 0.f, pd1 = 0.f;
#pragma unroll
        for (int nfr = 0; nfr < 4; nfr++) {
            const int col = nb * 128 + wn * 32 + nfr * 8 + (lane & 3) * 2;
            float* cc = acc[mf][nfr];
            if (EPI == 0) {
                const float as0 = attS[col], as1 = attS[col + 1];
                const float ad0 = attD[col], ad1 = attD[col + 1];
                ps0 += cc[0] * as0 + cc[1] * as1;
                pd0 += cc[0] * ad0 + cc[1] * ad1;
                ps1 += cc[2] * as0 + cc[3] * as1;
                pd1 += cc[2] * ad0 + cc[3] * ad1;
                __half2 v0 = __floats2half2_rn(cc[0], cc[1]);
                __half2 v1 = __floats2half2_rn(cc[2], cc[3]);
                if (m0 < M) *(__half2*)&g_xhh[(size_t)m0 * DIN + col] = v0;
                if (m1 < M) *(__half2*)&g_xhh[(size_t)m1 * DIN + col] = v1;
            } else if (EPI == 1) {
                char* img = outImg + (size_t)mtile128 * (2 * 4 * 16384);
                const int ir0 = mhalf * 64 + rl0;           // image row 0..127
                const float b0 = bias[col], b1 = bias[col + 1];
                const int ch = col >> 6, kk = col & 63;
                const size_t hiOff = (size_t)(0 * 4 + ch) * 16384;
                const size_t loOff = (size_t)(1 * 4 + ch) * 16384;
                if (m0 < M) {
                    uint32_t hp, lp;
                    split2h(geluf(cc[0] + b0), geluf(cc[1] + b1), hp, lp);
                    uint32_t off = SWZ(ir0 * 128 + kk * 2);
                    *(uint32_t*)(img + hiOff + off) = hp;
                    *(uint32_t*)(img + loOff + off) = lp;
                }
                if (m1 < M) {
                    uint32_t hp, lp;
                    split2h(geluf(cc[2] + b0), geluf(cc[3] + b1), hp, lp);
                    uint32_t off = SWZ((ir0 + 8) * 128 + kk * 2);
                    *(uint32_t*)(img + hiOff + off) = hp;
                    *(uint32_t*)(img + loOff + off) = lp;
                }
            } else {
                const float b0 = bias[col], b1 = bias[col + 1];
                if (m0 < M) {
                    const float2 rr = *(const float2*)&resid[(size_t)m0 * NTOT + col];
                    *(float2*)&outF[(size_t)m0 * NTOT + col] =
                        make_float2(cc[0] + b0 + rr.x, cc[1] + b1 + rr.y);
                }
                if (m1 < M) {
                    const float2 rr = *(const float2*)&resid[(size_t)m1 * NTOT + col];
                    *(float2*)&outF[(size_t)m1 * NTOT + col] =
                        make_float2(cc[2] + b0 + rr.x, cc[3] + b1 + rr.y);
                }
            }
        }
        if (EPI == 0) {
#pragma unroll
            for (int o = 1; o <= 2; o <<= 1) {
                ps0 += __shfl_xor_sync(0xffffffffu, ps0, o);
                pd0 += __shfl_xor_sync(0xffffffffu, pd0, o);
                ps1 += __shfl_xor_sync(0xffffffffu, ps1, o);
                pd1 += __shfl_xor_sync(0xffffffffu, pd1, o);
            }
            if ((lane & 3) == 0) {
                if (m0 < M) {
                    g_asrc[m0 * NHEAD + wn] = ps0;
                    g_adst[m0 * NHEAD + wn] = pd0;
                }
                if (m1 < M) {
                    g_asrc[m1 * NHEAD + wn] = ps1;
                    g_adst[m1 * NHEAD + wn] = pd1;
                }
            }
        }
    }
}

// ---- fused gather aggregation: softmax + weighted sum + +gat_b + resid + LN2 -
__global__ void csr_agg_kernel(const float* __restrict__ x,
                               const float* __restrict__ gat_b,
                               const float* __restrict__ g2,
                               const float* __restrict__ b2, int n, int Et) {
    int row  = blockIdx.x * 8 + (threadIdx.x >> 5);
    int lane = threadIdx.x & 31;
    if (row >= n) return;
    const int h = lane >> 3;
    const float adst_h = g_adst[row * NHEAD + h];
    const int p0 = g_rowp[row];
    const int p1 = (row == n - 1) ? Et : g_rowp[row + 1];

    float4 acc = make_float4(0.f, 0.f, 0.f, 0.f);
    float den = 0.f;
    for (int p = p0; p < p1; p++) {
        int s = g_col[p];
        float ex = expf(lrelu(g_asrc[s * NHEAD + h] + adst_h));
        den += ex;
        const uint2 raw = *(const uint2*)&g_xhh[(size_t)s * DIN + lane * 4];
        const float2 f0 = __half22float2(*(const __half2*)&raw.x);
        const float2 f1 = __half22float2(*(const __half2*)&raw.y);
        acc.x += f0.x * ex; acc.y += f0.y * ex;
        acc.z += f1.x * ex; acc.w += f1.y * ex;
    }
    float inv = 1.f / den;
    const float4 xv = *(const float4*)&x[(size_t)row * DIN + lane * 4];
    const float4 gb = *(const float4*)&gat_b[lane * 4];
    float4 h2;
    h2.x = acc.x * inv + gb.x + xv.x;
    h2.y = acc.y * inv + gb.y + xv.y;
    h2.z = acc.z * inv + gb.z + xv.z;
    h2.w = acc.w * inv + gb.w + xv.w;
    *(float4*)&g_h2[(size_t)row * DIN + lane * 4] = h2;

    float s  = warpSum(h2.x + h2.y + h2.z + h2.w);
    float sq = warpSum(h2.x * h2.x + h2.y * h2.y + h2.z * h2.z + h2.w * h2.w);
    float m = s * (1.f / DIN);
    float rin = rsqrtf(sq * (1.f / DIN) - m * m + EPSV);
    const float4 g = *(const float4*)&g2[lane * 4];
    const float4 b = *(const float4*)&b2[lane * 4];
    float4 o;
    o.x = (h2.x - m) * rin * g.x + b.x;
    o.y = (h2.y - m) * rin * g.y + b.y;
    o.z = (h2.z - m) * rin * g.z + b.z;
    o.w = (h2.w - m) * rin * g.w + b.w;
    int mtile = row >> 7, r = row & 127;
    int col0 = lane * 4, ch = col0 >> 6, kk = col0 & 63;
    uint32_t off = SWZ(r * 128 + kk * 2);
    char* base = g_A2 + (size_t)mtile * (2 * 2 * 16384);
    split_store8h(base, (size_t)(0 * 2 + ch) * 16384, (size_t)(1 * 2 + ch) * 16384, off, o);
}

// ---------------- launch ------------------------------------------------------
extern "C" void kernel_launch(void* const* d_in, const int* in_sizes, int n_in,
                              void* d_out, int out_size) {
    const float* x     = (const float*)d_in[0];
    const void*  ei    = d_in[1];
    const float* ln1_g = (const float*)d_in[2];
    const float* ln1_b = (const float*)d_in[3];
    const float* W     = (const float*)d_in[4];
    const float* att_s = (const float*)d_in[5];
    const float* att_d = (const float*)d_in[6];
    const float* gat_b = (const float*)d_in[7];
    const float* ln2_g = (const float*)d_in[8];
    const float* ln2_b = (const float*)d_in[9];
    const float* w1    = (const float*)d_in[10];
    const float* b1    = (const float*)d_in[11];
    const float* w2    = (const float*)d_in[12];
    const float* b2    = (const float*)d_in[13];
    float*       out   = (float*)d_out;

    const int n      = in_sizes[0] / DIN;
    const int E      = in_sizes[1] / 2;
    const int Et     = E + n;
    const int mtiles = (n + 127) / 128;
    const int mblks  = 2 * mtiles;
    const int nparts = (n + 1023) / 1024;

    float* ph2;  cudaGetSymbolAddress((void**)&ph2, g_h2);
    char*  pA1;  cudaGetSymbolAddress((void**)&pA1, g_A1);
    char*  pA2;  cudaGetSymbolAddress((void**)&pA2, g_A2);
    char*  pA3;  cudaGetSymbolAddress((void**)&pA3, g_A3);
    char*  pB1;  cudaGetSymbolAddress((void**)&pB1, g_B1);
    char*  pB2;  cudaGetSymbolAddress((void**)&pB2, g_B2);
    char*  pB3;  cudaGetSymbolAddress((void**)&pB3, g_B3);
    int*   pcnt; cudaGetSymbolAddress((void**)&pcnt, g_cnt);

    const int SMEM_BF = 98304;   // bf16 GEMM1: 2 x 48KB
    const int SMEM_F16 = 65536;  // fp16 GEMM2/3: 2 x 32KB
    cudaFuncSetAttribute(mma_gemm<128, 2, 0, 0>, cudaFuncAttributeMaxDynamicSharedMemorySize, SMEM_BF);
    cudaFuncSetAttribute(mma_gemm<256, 2, 1, 1>, cudaFuncAttributeMaxDynamicSharedMemorySize, SMEM_F16);
    cudaFuncSetAttribute(mma_gemm<128, 4, 2, 1>, cudaFuncAttributeMaxDynamicSharedMemorySize, SMEM_F16);

    // one-time resources (host-side only; no device memory)
    static cudaStream_t s2 = nullptr;
    static cudaEvent_t evFork = nullptr, evCsr = nullptr;
    if (!s2) {
        cudaStreamCreateWithFlags(&s2, cudaStreamNonBlocking);
        cudaEventCreateWithFlags(&evFork, cudaEventDisableTiming);
        cudaEventCreateWithFlags(&evCsr, cudaEventDisableTiming);
    }

    // fork: CSR build on side stream (independent of LN/bconv/GEMM1 path)
    cudaEventRecord(evFork, 0);
    cudaStreamWaitEvent(s2, evFork, 0);
    cudaMemsetAsync(pcnt, 0, (size_t)n * sizeof(int), s2);
    detect_kernel<<<1, 256, 0, s2>>>((const int*)ei, E);
    count_kernel<<<(Et + 255) / 256, 256, 0, s2>>>(ei, E, Et);
    scan_kernel<<<nparts, 256, 0, s2>>>(n);
    scatter_kernel<<<(Et + 255) / 256, 256, 0, s2>>>(Et);
    cudaEventRecord(evCsr, s2);

    // main path
    bconv_ln_kernel<<<BCONV_BLK + (n + 7) / 8, 256>>>(W, w1, w2, x, ln1_g, ln1_b, n);
    mma_gemm<128, 2, 0, 0><<<dim3(mblks, 1), 256, SMEM_BF>>>(
        pA1, pB1, nullptr, nullptr, nullptr, nullptr, att_s, att_d, n);

    // join: csr_agg needs both CSR and GEMM1 outputs
    cudaStreamWaitEvent(0, evCsr, 0);
    csr_agg_kernel<<<(n + 7) / 8, 256>>>(x, gat_b, ln2_g, ln2_b, n, Et);
    mma_gemm<256, 2, 1, 1><<<dim3(mblks, 2), 256, SMEM_F16>>>(
        pA2, pB2, b1, nullptr, nullptr, pA3, nullptr, nullptr, n);
    mma_gemm<128, 4, 2, 1><<<dim3(mblks, 1), 256, SMEM_F16>>>(
        pA3, pB3, b2, ph2, out, nullptr, nullptr, nullptr, n);
}

// round 16
// speedup vs baseline: 1.1877x; 1.0661x over previous
#include <cuda_runtime.h>
#include <cuda_bf16.h>
#include <cuda_fp16.h>
#include <math.h>
#include <float.h>
#include <stdint.h>

#define DIN   128
#define NHEAD 4
#define EPSV  1e-5f
#define SLOPE 0.2f
#define MAXN  50000
#define MAXE  800000
#define MAXT  392            // max M tiles of 128

// ---------------- scratch (static device globals; no allocation) ------------
__device__ __half g_xhh[(size_t)MAXN * DIN];            // h @ W (fp16 messages)
__device__ float  g_h2 [(size_t)MAXN * DIN];            // gat out + residual
__device__ float  g_asrc[(size_t)MAXN * NHEAD];
__device__ float  g_adst[(size_t)MAXN * NHEAD];
__device__ int    g_src [MAXE + MAXN];
__device__ int    g_dst [MAXE + MAXN];
__device__ int    g_ord [MAXE + MAXN];                  // per-edge ordinal within dst row
__device__ int    g_col [MAXE + MAXN];                  // CSR: src per slot
__device__ int    g_cnt [MAXN];
__device__ int    g_rowp[MAXN + 1];

// A-operand images, pre-swizzled SMEM tile layout:
// [mtile][sel(hi=0,lo=1)][chunk][128 rows x 128 bytes, SW128]   (chunk = 64 k-vals)
__device__ __align__(16) char g_A1[(size_t)MAXT * 2 * 2 * 16384];  // LN1(x)  fp16 hi/lo, K=128
__device__ __align__(16) char g_A2[(size_t)MAXT * 2 * 2 * 16384];  // LN2(h2) fp16 hi/lo, K=128
__device__ __align__(16) char g_A3[(size_t)MAXT * 2 * 4 * 16384];  // ffn1    fp16 hi/lo, K=256
// B images: fp16 single [ch][N rows x 128 bytes, SW128]
__device__ __align__(16) char g_B1[2 * 128 * 128];
__device__ __align__(16) char g_B2[2 * 256 * 128];
__device__ __align__(16) char g_B3[4 * 128 * 128];

// ---------------- helpers ------------------------------------------------------
#define SWZ(o) ((uint32_t)(o) ^ ((((uint32_t)(o)) >> 3) & 0x70u))

__device__ __forceinline__ uint32_t smem_u32(const void* p) {
    uint32_t a;
    asm("{ .reg .u64 t; cvta.to.shared.u64 t, %1; cvt.u32.u64 %0, t; }" : "=r"(a) : "l"(p));
    return a;
}
__device__ __forceinline__ void ldsm4(uint32_t* r, uint32_t addr) {
    asm volatile("ldmatrix.sync.aligned.m8n8.x4.shared.b16 {%0,%1,%2,%3}, [%4];"
                 : "=r"(r[0]), "=r"(r[1]), "=r"(r[2]), "=r"(r[3]) : "r"(addr));
}
__device__ __forceinline__ void mma16816h(float* c, const uint32_t* a, const uint32_t* b) {
    asm volatile("mma.sync.aligned.m16n8k16.row.col.f32.f16.f16.f32 "
                 "{%0,%1,%2,%3}, {%4,%5,%6,%7}, {%8,%9}, {%0,%1,%2,%3};"
                 : "+f"(c[0]), "+f"(c[1]), "+f"(c[2]), "+f"(c[3])
                 : "r"(a[0]), "r"(a[1]), "r"(a[2]), "r"(a[3]), "r"(b[0]), "r"(b[1]));
}
__device__ __forceinline__ void cpasync16(uint32_t dst, const void* src) {
    asm volatile("cp.async.cg.shared.global [%0], [%1], 16;" :: "r"(dst), "l"(src) : "memory");
}
__device__ __forceinline__ float warpSum(float v) {
#pragma unroll
    for (int o = 16; o; o >>= 1) v += __shfl_xor_sync(0xffffffffu, v, o);
    return v;
}
__device__ __forceinline__ float geluf(float v) {
    return 0.5f * v * (1.f + erff(v * 0.70710678118654752440f));
}
__device__ __forceinline__ float lrelu(float v) { return v > 0.f ? v : SLOPE * v; }

// fp16 hi/lo split (pairs)
__device__ __forceinline__ void split2h(float v0, float v1, uint32_t& hi, uint32_t& lo) {
    __half h0 = __float2half_rn(v0), h1 = __float2half_rn(v1);
    __half l0 = __float2half_rn(v0 - __half2float(h0));
    __half l1 = __float2half_rn(v1 - __half2float(h1));
    __half2 hp; hp.x = h0; hp.y = h1;
    __half2 lp; lp.x = l0; lp.y = l1;
    hi = *(uint32_t*)&hp; lo = *(uint32_t*)&lp;
}
__device__ __forceinline__ void split_store8h(char* base, size_t hiOff, size_t loOff,
                                              uint32_t off, float4 o) {
    uint32_t h0, l0, h1, l1;
    split2h(o.x, o.y, h0, l0);
    split2h(o.z, o.w, h1, l1);
    *(uint32_t*)(base + hiOff + off)     = h0;
    *(uint32_t*)(base + hiOff + off + 4) = h1;
    *(uint32_t*)(base + loOff + off)     = l0;
    *(uint32_t*)(base + loOff + off + 4) = l1;
}

// ---------------- count: inline dtype detect + convert + degree + ordinal -----
__global__ void count_kernel(const void* __restrict__ ei, int E, int Et) {
    __shared__ int any;
    const int tid = threadIdx.x;
    if (tid == 0) any = 0;
    __syncthreads();
    {
        const int* p32 = (const int*)ei;
        int samples = min(E, 512), local = 0;
        for (int k = tid; k < samples; k += 256)
            if (p32[2 * k + 1] != 0) local = 1;
        if (local) atomicOr(&any, 1);
    }
    __syncthreads();
    const int is64 = !any;

    int e = blockIdx.x * blockDim.x + tid;
    if (e >= Et) return;
    int s, d;
    if (e < E) {
        if (is64) {
            const long long* p = (const long long*)ei;
            s = (int)p[e]; d = (int)p[(size_t)E + e];
        } else {
            const int* p = (const int*)ei;
            s = p[e]; d = p[E + e];
        }
    } else { s = d = e - E; }
    g_src[e] = s; g_dst[e] = d;
    g_ord[e] = atomicAdd(&g_cnt[d], 1);
}

// merged scan: each block self-computes its chunk base
__global__ void scan_kernel(int n) {
    __shared__ int wsum[8];
    __shared__ int red[8];
    __shared__ int chunkBase;
    int b = blockIdx.x, tid = threadIdx.x;
    int lane = tid & 31, wid = tid >> 5;
    {
        int pre = b * 1024;
        int s = 0;
        for (int i = tid; i < pre; i += 256) s += g_cnt[i];
#pragma unroll
        for (int o = 16; o; o >>= 1) s += __shfl_xor_sync(0xffffffffu, s, o);
        if (lane == 0) red[wid] = s;
        __syncthreads();
        if (tid == 0) {
            int t = 0;
#pragma unroll
            for (int w = 0; w < 8; w++) t += red[w];
            chunkBase = t;
        }
    }
    int i0 = b * 1024 + tid * 4;
    int v[4];
#pragma unroll
    for (int j = 0; j < 4; j++) v[j] = (i0 + j < n) ? g_cnt[i0 + j] : 0;
    int tsum = v[0] + v[1] + v[2] + v[3];
    int incl = tsum;
#pragma unroll
    for (int o = 1; o < 32; o <<= 1) {
        int t = __shfl_up_sync(0xffffffffu, incl, o);
        if (lane >= o) incl += t;
    }
    if (lane == 31) wsum[wid] = incl;
    __syncthreads();
    if (tid == 0) {
        int s = 0;
#pragma unroll
        for (int w = 0; w < 8; w++) { int t = wsum[w]; wsum[w] = s; s += t; }
    }
    __syncthreads();
    int run = chunkBase + wsum[wid] + incl - tsum;
#pragma unroll
    for (int j = 0; j < 4; j++) {
        if (i0 + j < n) g_rowp[i0 + j] = run;
        run += v[j];
    }
}

// atomic-free scatter: pos = rowp[dst] + ord
__global__ void scatter_kernel(int Et) {
    int e = blockIdx.x * blockDim.x + threadIdx.x;
    if (e >= Et) return;
    int d = g_dst[e];
    g_col[g_rowp[d] + g_ord[e]] = g_src[e];
}

// ---------------- fused bconv + LN1->A1 image ---------------------------------
// W/w1/w2 -> fp16 single (g_B1/g_B2/g_B3)
#define BCONV_TOT (128*128 + 128*256 + 256*128)
#define BCONV_BLK ((BCONV_TOT + 255) / 256)
__global__ void bconv_ln_kernel(const float* __restrict__ W,
                                const float* __restrict__ w1,
                                const float* __restrict__ w2,
                                const float* __restrict__ in,
                                const float* __restrict__ gg,
                                const float* __restrict__ bb, int n) {
    if (blockIdx.x < BCONV_BLK) {
        int idx = blockIdx.x * 256 + threadIdx.x;
        if (idx < 128 * 128) {
            int k = idx / 128, nn = idx % 128;
            float v = W[(size_t)k * 128 + nn];
            int ch = k >> 6, kk = k & 63;
            uint32_t off = SWZ(nn * 128 + kk * 2);
            *(__half*)(g_B1 + (size_t)ch * (128 * 128) + off) = __float2half_rn(v);
        } else if (idx < 128*128 + 128*256) {
            idx -= 128 * 128;
            int k = idx / 256, nn = idx % 256;
            float v = w1[(size_t)k * 256 + nn];
            int ch = k >> 6, kk = k & 63;
            uint32_t off = SWZ(nn * 128 + kk * 2);
            *(__half*)(g_B2 + (size_t)ch * (256 * 128) + off) = __float2half_rn(v);
        } else if (idx < BCONV_TOT) {
            idx -= 128*128 + 128*256;
            int k = idx / 128, nn = idx % 128;
            float v = w2[(size_t)k * 128 + nn];
            int ch = k >> 6, kk = k & 63;
            uint32_t off = SWZ(nn * 128 + kk * 2);
            *(__half*)(g_B3 + (size_t)ch * (128 * 128) + off) = __float2half_rn(v);
        }
        return;
    }
    int row  = (blockIdx.x - BCONV_BLK) * 8 + (threadIdx.x >> 5);
    int lane = threadIdx.x & 31;
    if (row >= n) return;
    const float4 v = *(const float4*)&in[(size_t)row * DIN + lane * 4];
    float s  = warpSum(v.x + v.y + v.z + v.w);
    float sq = warpSum(v.x * v.x + v.y * v.y + v.z * v.z + v.w * v.w);
    float m = s * (1.f / DIN);
    float inv = rsqrtf(sq * (1.f / DIN) - m * m + EPSV);
    const float4 g = *(const float4*)&gg[lane * 4];
    const float4 b = *(const float4*)&bb[lane * 4];
    float4 o;
    o.x = (v.x - m) * inv * g.x + b.x;
    o.y = (v.y - m) * inv * g.y + b.y;
    o.z = (v.z - m) * inv * g.z + b.z;
    o.w = (v.w - m) * inv * g.w + b.w;
    int mtile = row >> 7, r = row & 127;
    int col0 = lane * 4, ch = col0 >> 6, kk = col0 & 63;
    uint32_t off = SWZ(r * 128 + kk * 2);
    char* base = g_A1 + (size_t)mtile * (2 * 2 * 16384);
    split_store8h(base, (size_t)(0 * 2 + ch) * 16384, (size_t)(1 * 2 + ch) * 16384, off, o);
}

// ---------------- warp-MMA GEMM, 64x128 block tile, 2 CTAs/SM -----------------
// fp16: A hi/lo x B single, 2-MMA compensation.
// EPI 0: fp16 xh table + attention logits. EPI 1: gelu -> A3 fp16 image. EPI 2: +bias+resid.
template <int NTOT, int NCH, int EPI>
__global__ void __launch_bounds__(256, 2)
mma_gemm(const char* __restrict__ Aimg, const char* __restrict__ Bimg,
         const float* __restrict__ bias, const float* __restrict__ resid,
         float* __restrict__ outF, char* __restrict__ outImg,
         const float* __restrict__ attS, const float* __restrict__ attD, int M) {
    extern __shared__ char smem[];
    const uint32_t sb = smem_u32(smem);
    const int tid = threadIdx.x, wid = tid >> 5, lane = tid & 31;
    const int mblk = blockIdx.x, nb = blockIdx.y;
    const int mtile128 = mblk >> 1, mhalf = mblk & 1;
    const int wm = wid & 1, wn = wid >> 1;
    constexpr int BUFS = 32768;   // stage bytes: Ah 8K + Al 8K + B 16K

    const char* Ab = Aimg + (size_t)mtile128 * (2 * NCH * 16384) + (size_t)mhalf * 8192;

    int rowTA[2], rowTB[2];
#pragma unroll
    for (int mf = 0; mf < 2; mf++)
        rowTA[mf] = (wm * 32 + mf * 16 + (lane & 15)) * 128 + (lane >> 4) * 16;
#pragma unroll
    for (int nfg = 0; nfg < 2; nfg++)
        rowTB[nfg] = (wn * 32 + nfg * 16 + (lane >> 4) * 8 + (lane & 7)) * 128
                   + ((lane >> 3) & 1) * 16;

    float acc[2][4][4];
#pragma unroll
    for (int i = 0; i < 2; i++)
#pragma unroll
        for (int j = 0; j < 4; j++)
#pragma unroll
            for (int q = 0; q < 4; q++) acc[i][j][q] = 0.f;

    auto stage = [&](int c, int bufIdx) {
        const char* aSrc[2] = {
            Ab + (size_t)(0 * NCH + c) * 16384,
            Ab + (size_t)(1 * NCH + c) * 16384
        };
        uint32_t dbase = sb + bufIdx * BUFS;
#pragma unroll
        for (int sel = 0; sel < 2; sel++) {
#pragma unroll
            for (int i = 0; i < 2; i++) {
                int ofs = (tid + 256 * i) * 16;
                cpasync16(dbase + sel * 8192 + ofs, aSrc[sel] + ofs);
            }
        }
        const char* bSrc = Bimg + (size_t)c * ((size_t)NTOT * 128) + (size_t)nb * 16384;
#pragma unroll
        for (int i = 0; i < 4; i++) {
            int ofs = (tid + 256 * i) * 16;
            cpasync16(dbase + 16384 + ofs, bSrc + ofs);
        }
        asm volatile("cp.async.commit_group;" ::: "memory");
    };

    stage(0, 0);
    int buf = 0;
    for (int c = 0; c < NCH; c++) {
        if (c + 1 < NCH) {
            stage(c + 1, buf ^ 1);
            asm volatile("cp.async.wait_group 1;" ::: "memory");
        } else {
            asm volatile("cp.async.wait_group 0;" ::: "memory");
        }
        __syncthreads();

        const uint32_t bbase = sb + buf * BUFS;
#pragma unroll
        for (int kk = 0; kk < 4; kk++) {
            uint32_t ah[2][4], al[2][4];
#pragma unroll
            for (int mf = 0; mf < 2; mf++) {
                uint32_t off = SWZ(rowTA[mf] + kk * 32);
                ldsm4(ah[mf], bbase + off);
                ldsm4(al[mf], bbase + 8192 + off);
            }
#pragma unroll
            for (int nfg = 0; nfg < 2; nfg++) {
                uint32_t off = SWZ(rowTB[nfg] + kk * 32);
                uint32_t bq[4];
                ldsm4(bq, bbase + 16384 + off);
#pragma unroll
                for (int mf = 0; mf < 2; mf++) {
                    mma16816h(acc[mf][2 * nfg],     ah[mf], bq);
                    mma16816h(acc[mf][2 * nfg],     al[mf], bq);
                    mma16816h(acc[mf][2 * nfg + 1], ah[mf], bq + 2);
                    mma16816h(acc[mf][2 * nfg + 1], al[mf], bq + 2);
                }
            }
        }
        __syncthreads();
        buf ^= 1;
    }

    // ---------------- epilogue ----------------
#pragma unroll
    for (int mf = 0; mf < 2; mf++) {
        const int rl0 = wm * 32 + mf * 16 + (lane >> 2);   // local row 0..63
        const int m0 = mblk * 64 + rl0;
        const int m1 = m0 + 8;
        float ps0 = 0.f, pd0 = 0.f, ps1 = 0.f, pd1 = 0.f;
#pragma unroll
        for (int nfr = 0; nfr < 4; nfr++) {
            const int col = nb * 128 + wn * 32 + nfr * 8 + (lane & 3) * 2;
            float* cc = acc[mf][nfr];
            if (EPI == 0) {
                const float as0 = attS[col], as1 = attS[col + 1];
                const float ad0 = attD[col], ad1 = attD[col + 1];
                ps0 += cc[0] * as0 + cc[1] * as1;
                pd0 += cc[0] * ad0 + cc[1] * ad1;
                ps1 += cc[2] * as0 + cc[3] * as1;
                pd1 += cc[2] * ad0 + cc[3] * ad1;
                __half2 v0 = __floats2half2_rn(cc[0], cc[1]);
                __half2 v1 = __floats2half2_rn(cc[2], cc[3]);
                if (m0 < M) *(__half2*)&g_xhh[(size_t)m0 * DIN + col] = v0;
                if (m1 < M) *(__half2*)&g_xhh[(size_t)m1 * DIN + col] = v1;
            } else if (EPI == 1) {
                char* img = outImg + (size_t)mtile128 * (2 * 4 * 16384);
                const int ir0 = mhalf * 64 + rl0;           // image row 0..127
                const float b0 = bias[col], b1 = bias[col + 1];
                const int ch = col >> 6, kk = col & 63;
                const size_t hiOff = (size_t)(0 * 4 + ch) * 16384;
                const size_t loOff = (size_t)(1 * 4 + ch) * 16384;
                if (m0 < M) {
                    uint32_t hp, lp;
                    split2h(geluf(cc[0] + b0), geluf(cc[1] + b1), hp, lp);
                    uint32_t off = SWZ(ir0 * 128 + kk * 2);
                    *(uint32_t*)(img + hiOff + off) = hp;
                    *(uint32_t*)(img + loOff + off) = lp;
                }
                if (m1 < M) {
                    uint32_t hp, lp;
                    split2h(geluf(cc[2] + b0), geluf(cc[3] + b1), hp, lp);
                    uint32_t off = SWZ((ir0 + 8) * 128 + kk * 2);
                    *(uint32_t*)(img + hiOff + off) = hp;
                    *(uint32_t*)(img + loOff + off) = lp;
                }
            } else {
                const float b0 = bias[col], b1 = bias[col + 1];
                if (m0 < M) {
                    const float2 rr = *(const float2*)&resid[(size_t)m0 * NTOT + col];
                    *(float2*)&outF[(size_t)m0 * NTOT + col] =
                        make_float2(cc[0] + b0 + rr.x, cc[1] + b1 + rr.y);
                }
                if (m1 < M) {
                    const float2 rr = *(const float2*)&resid[(size_t)m1 * NTOT + col];
                    *(float2*)&outF[(size_t)m1 * NTOT + col] =
                        make_float2(cc[2] + b0 + rr.x, cc[3] + b1 + rr.y);
                }
            }
        }
        if (EPI == 0) {
#pragma unroll
            for (int o = 1; o <= 2; o <<= 1) {
                ps0 += __shfl_xor_sync(0xffffffffu, ps0, o);
                pd0 += __shfl_xor_sync(0xffffffffu, pd0, o);
                ps1 += __shfl_xor_sync(0xffffffffu, ps1, o);
                pd1 += __shfl_xor_sync(0xffffffffu, pd1, o);
            }
            if ((lane & 3) == 0) {
                if (m0 < M) {
                    g_asrc[m0 * NHEAD + wn] = ps0;
                    g_adst[m0 * NHEAD + wn] = pd0;
                }
                if (m1 < M) {
                    g_asrc[m1 * NHEAD + wn] = ps1;
                    g_adst[m1 * NHEAD + wn] = pd1;
                }
            }
        }
    }
}

// ---- fused gather aggregation: softmax + weighted sum + +gat_b + resid + LN2 -
__global__ void csr_agg_kernel(const float* __restrict__ x,
                               const float* __restrict__ gat_b,
                               const float* __restrict__ g2,
                               const float* __restrict__ b2, int n, int Et) {
    int row  = blockIdx.x * 8 + (threadIdx.x >> 5);
    int lane = threadIdx.x & 31;
    if (row >= n) return;
    const int h = lane >> 3;
    const float adst_h = g_adst[row * NHEAD + h];
    const int p0 = g_rowp[row];
    const int p1 = (row == n - 1) ? Et : g_rowp[row + 1];

    float4 acc = make_float4(0.f, 0.f, 0.f, 0.f);
    float den = 0.f;
    for (int p = p0; p < p1; p++) {
        int s = g_col[p];
        float ex = expf(lrelu(g_asrc[s * NHEAD + h] + adst_h));
        den += ex;
        const uint2 raw = *(const uint2*)&g_xhh[(size_t)s * DIN + lane * 4];
        const float2 f0 = __half22float2(*(const __half2*)&raw.x);
        const float2 f1 = __half22float2(*(const __half2*)&raw.y);
        acc.x += f0.x * ex; acc.y += f0.y * ex;
        acc.z += f1.x * ex; acc.w += f1.y * ex;
    }
    float inv = 1.f / den;
    const float4 xv = *(const float4*)&x[(size_t)row * DIN + lane * 4];
    const float4 gb = *(const float4*)&gat_b[lane * 4];
    float4 h2;
    h2.x = acc.x * inv + gb.x + xv.x;
    h2.y = acc.y * inv + gb.y + xv.y;
    h2.z = acc.z * inv + gb.z + xv.z;
    h2.w = acc.w * inv + gb.w + xv.w;
    *(float4*)&g_h2[(size_t)row * DIN + lane * 4] = h2;

    float s  = warpSum(h2.x + h2.y + h2.z + h2.w);
    float sq = warpSum(h2.x * h2.x + h2.y * h2.y + h2.z * h2.z + h2.w * h2.w);
    float m = s * (1.f / DIN);
    float rin = rsqrtf(sq * (1.f / DIN) - m * m + EPSV);
    const float4 g = *(const float4*)&g2[lane * 4];
    const float4 b = *(const float4*)&b2[lane * 4];
    float4 o;
    o.x = (h2.x - m) * rin * g.x + b.x;
    o.y = (h2.y - m) * rin * g.y + b.y;
    o.z = (h2.z - m) * rin * g.z + b.z;
    o.w = (h2.w - m) * rin * g.w + b.w;
    int mtile = row >> 7, r = row & 127;
    int col0 = lane * 4, ch = col0 >> 6, kk = col0 & 63;
    uint32_t off = SWZ(r * 128 + kk * 2);
    char* base = g_A2 + (size_t)mtile * (2 * 2 * 16384);
    split_store8h(base, (size_t)(0 * 2 + ch) * 16384, (size_t)(1 * 2 + ch) * 16384, off, o);
}

// ---------------- launch ------------------------------------------------------
extern "C" void kernel_launch(void* const* d_in, const int* in_sizes, int n_in,
                              void* d_out, int out_size) {
    const float* x     = (const float*)d_in[0];
    const void*  ei    = d_in[1];
    const float* ln1_g = (const float*)d_in[2];
    const float* ln1_b = (const float*)d_in[3];
    const float* W     = (const float*)d_in[4];
    const float* att_s = (const float*)d_in[5];
    const float* att_d = (const float*)d_in[6];
    const float* gat_b = (const float*)d_in[7];
    const float* ln2_g = (const float*)d_in[8];
    const float* ln2_b = (const float*)d_in[9];
    const float* w1    = (const float*)d_in[10];
    const float* b1    = (const float*)d_in[11];
    const float* w2    = (const float*)d_in[12];
    const float* b2    = (const float*)d_in[13];
    float*       out   = (float*)d_out;

    const int n      = in_sizes[0] / DIN;
    const int E      = in_sizes[1] / 2;
    const int Et     = E + n;
    const int mtiles = (n + 127) / 128;
    const int mblks  = 2 * mtiles;
    const int nparts = (n + 1023) / 1024;

    float* ph2;  cudaGetSymbolAddress((void**)&ph2, g_h2);
    char*  pA1;  cudaGetSymbolAddress((void**)&pA1, g_A1);
    char*  pA2;  cudaGetSymbolAddress((void**)&pA2, g_A2);
    char*  pA3;  cudaGetSymbolAddress((void**)&pA3, g_A3);
    char*  pB1;  cudaGetSymbolAddress((void**)&pB1, g_B1);
    char*  pB2;  cudaGetSymbolAddress((void**)&pB2, g_B2);
    char*  pB3;  cudaGetSymbolAddress((void**)&pB3, g_B3);
    int*   pcnt; cudaGetSymbolAddress((void**)&pcnt, g_cnt);

    const int SMEM = 65536;   // fp16: 2 x 32KB double-buffered -> 2 CTAs/SM
    cudaFuncSetAttribute(mma_gemm<128, 2, 0>, cudaFuncAttributeMaxDynamicSharedMemorySize, SMEM);
    cudaFuncSetAttribute(mma_gemm<256, 2, 1>, cudaFuncAttributeMaxDynamicSharedMemorySize, SMEM);
    cudaFuncSetAttribute(mma_gemm<128, 4, 2>, cudaFuncAttributeMaxDynamicSharedMemorySize, SMEM);

    // one-time resources (host-side only; no device memory)
    static cudaStream_t s2 = nullptr;
    static cudaEvent_t evFork = nullptr, evCsr = nullptr;
    if (!s2) {
        cudaStreamCreateWithFlags(&s2, cudaStreamNonBlocking);
        cudaEventCreateWithFlags(&evFork, cudaEventDisableTiming);
        cudaEventCreateWithFlags(&evCsr, cudaEventDisableTiming);
    }

    // fork: CSR build on side stream (independent of LN/bconv/GEMM1 path)
    cudaEventRecord(evFork, 0);
    cudaStreamWaitEvent(s2, evFork, 0);
    cudaMemsetAsync(pcnt, 0, (size_t)n * sizeof(int), s2);
    count_kernel<<<(Et + 255) / 256, 256, 0, s2>>>(ei, E, Et);
    scan_kernel<<<nparts, 256, 0, s2>>>(n);
    scatter_kernel<<<(Et + 255) / 256, 256, 0, s2>>>(Et);
    cudaEventRecord(evCsr, s2);

    // main path
    bconv_ln_kernel<<<BCONV_BLK + (n + 7) / 8, 256>>>(W, w1, w2, x, ln1_g, ln1_b, n);
    mma_gemm<128, 2, 0><<<dim3(mblks, 1), 256, SMEM>>>(
        pA1, pB1, nullptr, nullptr, nullptr, nullptr, att_s, att_d, n);

    // join: csr_agg needs both CSR and GEMM1 outputs
    cudaStreamWaitEvent(0, evCsr, 0);
    csr_agg_kernel<<<(n + 7) / 8, 256>>>(x, gat_b, ln2_g, ln2_b, n, Et);
    mma_gemm<256, 2, 1><<<dim3(mblks, 2), 256, SMEM>>>(
        pA2, pB2, b1, nullptr, nullptr, pA3, nullptr, nullptr, n);
    mma_gemm<128, 4, 2><<<dim3(mblks, 1), 256, SMEM>>>(
        pA3, pB3, b2, ph2, out, nullptr, nullptr, nullptr, n);
}

// round 17
// speedup vs baseline: 1.1995x; 1.0100x over previous
#include <cuda_runtime.h>
#include <cuda_bf16.h>
#include <cuda_fp16.h>
#include <math.h>
#include <float.h>
#include <stdint.h>

#define DIN   128
#define NHEAD 4
#define EPSV  1e-5f
#define SLOPE 0.2f
#define MAXN  50000
#define MAXE  800000
#define MAXT  392            // max M tiles of 128

// ---------------- scratch (static device globals; no allocation) ------------
__device__ __half g_xhh[(size_t)MAXN * DIN];            // h @ W (fp16 messages)
__device__ float  g_h2 [(size_t)MAXN * DIN];            // gat out + residual
__device__ float  g_asrc[(size_t)MAXN * NHEAD];
__device__ float  g_adst[(size_t)MAXN * NHEAD];
__device__ int    g_src [MAXE + MAXN];
__device__ int    g_dst [MAXE + MAXN];
__device__ int    g_ord [MAXE + MAXN];                  // per-edge ordinal within dst row
__device__ int    g_col [MAXE + MAXN];                  // CSR: src per slot
__device__ int    g_cnt [MAXN];                         // zero-init; re-zeroed by scatter
__device__ int    g_rowp[MAXN + 1];

// A-operand images, pre-swizzled SMEM tile layout:
// [mtile][sel(hi=0,lo=1)][chunk][128 rows x 128 bytes, SW128]   (chunk = 64 k-vals)
__device__ __align__(16) char g_A1[(size_t)MAXT * 2 * 2 * 16384];  // LN1(x)  fp16 hi/lo, K=128
__device__ __align__(16) char g_A2[(size_t)MAXT * 2 * 2 * 16384];  // LN2(h2) fp16 hi/lo, K=128
__device__ __align__(16) char g_A3[(size_t)MAXT * 2 * 4 * 16384];  // ffn1    fp16 hi/lo, K=256
// B images: fp16 single [ch][N rows x 128 bytes, SW128]
__device__ __align__(16) char g_B1[2 * 128 * 128];
__device__ __align__(16) char g_B2[2 * 256 * 128];
__device__ __align__(16) char g_B3[4 * 128 * 128];

// ---------------- helpers ------------------------------------------------------
#define SWZ(o) ((uint32_t)(o) ^ ((((uint32_t)(o)) >> 3) & 0x70u))

__device__ __forceinline__ uint32_t smem_u32(const void* p) {
    uint32_t a;
    asm("{ .reg .u64 t; cvta.to.shared.u64 t, %1; cvt.u32.u64 %0, t; }" : "=r"(a) : "l"(p));
    return a;
}
__device__ __forceinline__ void ldsm4(uint32_t* r, uint32_t addr) {
    asm volatile("ldmatrix.sync.aligned.m8n8.x4.shared.b16 {%0,%1,%2,%3}, [%4];"
                 : "=r"(r[0]), "=r"(r[1]), "=r"(r[2]), "=r"(r[3]) : "r"(addr));
}
__device__ __forceinline__ void mma16816h(float* c, const uint32_t* a, const uint32_t* b) {
    asm volatile("mma.sync.aligned.m16n8k16.row.col.f32.f16.f16.f32 "
                 "{%0,%1,%2,%3}, {%4,%5,%6,%7}, {%8,%9}, {%0,%1,%2,%3};"
                 : "+f"(c[0]), "+f"(c[1]), "+f"(c[2]), "+f"(c[3])
                 : "r"(a[0]), "r"(a[1]), "r"(a[2]), "r"(a[3]), "r"(b[0]), "r"(b[1]));
}
__device__ __forceinline__ void cpasync16(uint32_t dst, const void* src) {
    asm volatile("cp.async.cg.shared.global [%0], [%1], 16;" :: "r"(dst), "l"(src) : "memory");
}
__device__ __forceinline__ float warpSum(float v) {
#pragma unroll
    for (int o = 16; o; o >>= 1) v += __shfl_xor_sync(0xffffffffu, v, o);
    return v;
}
__device__ __forceinline__ float geluf(float v) {
    return 0.5f * v * (1.f + erff(v * 0.70710678118654752440f));
}
__device__ __forceinline__ float lrelu(float v) { return v > 0.f ? v : SLOPE * v; }

// fp16 hi/lo split (pairs)
__device__ __forceinline__ void split2h(float v0, float v1, uint32_t& hi, uint32_t& lo) {
    __half h0 = __float2half_rn(v0), h1 = __float2half_rn(v1);
    __half l0 = __float2half_rn(v0 - __half2float(h0));
    __half l1 = __float2half_rn(v1 - __half2float(h1));
    __half2 hp; hp.x = h0; hp.y = h1;
    __half2 lp; lp.x = l0; lp.y = l1;
    hi = *(uint32_t*)&hp; lo = *(uint32_t*)&lp;
}
__device__ __forceinline__ void split_store8h(char* base, size_t hiOff, size_t loOff,
                                              uint32_t off, float4 o) {
    uint32_t h0, l0, h1, l1;
    split2h(o.x, o.y, h0, l0);
    split2h(o.z, o.w, h1, l1);
    *(uint32_t*)(base + hiOff + off)     = h0;
    *(uint32_t*)(base + hiOff + off + 4) = h1;
    *(uint32_t*)(base + loOff + off)     = l0;
    *(uint32_t*)(base + loOff + off + 4) = l1;
}

// ---------------- count: inline dtype detect + convert + degree + ordinal -----
__global__ void count_kernel(const void* __restrict__ ei, int E, int Et) {
    __shared__ int any;
    const int tid = threadIdx.x;
    if (tid == 0) any = 0;
    __syncthreads();
    {
        const int* p32 = (const int*)ei;
        int samples = min(E, 512), local = 0;
        for (int k = tid; k < samples; k += 256)
            if (p32[2 * k + 1] != 0) local = 1;
        if (local) atomicOr(&any, 1);
    }
    __syncthreads();
    const int is64 = !any;

    int e = blockIdx.x * blockDim.x + tid;
    if (e >= Et) return;
    int s, d;
    if (e < E) {
        if (is64) {
            const long long* p = (const long long*)ei;
            s = (int)p[e]; d = (int)p[(size_t)E + e];
        } else {
            const int* p = (const int*)ei;
            s = p[e]; d = p[E + e];
        }
    } else { s = d = e - E; }
    g_src[e] = s; g_dst[e] = d;
    g_ord[e] = atomicAdd(&g_cnt[d], 1);
}

// merged scan: each block self-computes its chunk base
__global__ void scan_kernel(int n) {
    __shared__ int wsum[8];
    __shared__ int red[8];
    __shared__ int chunkBase;
    int b = blockIdx.x, tid = threadIdx.x;
    int lane = tid & 31, wid = tid >> 5;
    {
        int pre = b * 1024;
        int s = 0;
        for (int i = tid; i < pre; i += 256) s += g_cnt[i];
#pragma unroll
        for (int o = 16; o; o >>= 1) s += __shfl_xor_sync(0xffffffffu, s, o);
        if (lane == 0) red[wid] = s;
        __syncthreads();
        if (tid == 0) {
            int t = 0;
#pragma unroll
            for (int w = 0; w < 8; w++) t += red[w];
            chunkBase = t;
        }
    }
    int i0 = b * 1024 + tid * 4;
    int v[4];
#pragma unroll
    for (int j = 0; j < 4; j++) v[j] = (i0 + j < n) ? g_cnt[i0 + j] : 0;
    int tsum = v[0] + v[1] + v[2] + v[3];
    int incl = tsum;
#pragma unroll
    for (int o = 1; o < 32; o <<= 1) {
        int t = __shfl_up_sync(0xffffffffu, incl, o);
        if (lane >= o) incl += t;
    }
    if (lane == 31) wsum[wid] = incl;
    __syncthreads();
    if (tid == 0) {
        int s = 0;
#pragma unroll
        for (int w = 0; w < 8; w++) { int t = wsum[w]; wsum[w] = s; s += t; }
    }
    __syncthreads();
    int run = chunkBase + wsum[wid] + incl - tsum;
#pragma unroll
    for (int j = 0; j < 4; j++) {
        if (i0 + j < n) g_rowp[i0 + j] = run;
        run += v[j];
    }
}

// atomic-free scatter: pos = rowp[dst] + ord. Also re-zeroes g_cnt for the
// next graph replay (scan has consumed it; count is the next reader).
__global__ void scatter_kernel(int Et, int n) {
    int e = blockIdx.x * blockDim.x + threadIdx.x;
    if (e < n) g_cnt[e] = 0;
    if (e >= Et) return;
    int d = g_dst[e];
    g_col[g_rowp[d] + g_ord[e]] = g_src[e];
}

// ---------------- fused bconv + LN1->A1 image ---------------------------------
// W/w1/w2 -> fp16 single (g_B1/g_B2/g_B3)
#define BCONV_TOT (128*128 + 128*256 + 256*128)
#define BCONV_BLK ((BCONV_TOT + 255) / 256)
__global__ void bconv_ln_kernel(const float* __restrict__ W,
                                const float* __restrict__ w1,
                                const float* __restrict__ w2,
                                const float* __restrict__ in,
                                const float* __restrict__ gg,
                                const float* __restrict__ bb, int n) {
    if (blockIdx.x < BCONV_BLK) {
        int idx = blockIdx.x * 256 + threadIdx.x;
        if (idx < 128 * 128) {
            int k = idx / 128, nn = idx % 128;
            float v = W[(size_t)k * 128 + nn];
            int ch = k >> 6, kk = k & 63;
            uint32_t off = SWZ(nn * 128 + kk * 2);
            *(__half*)(g_B1 + (size_t)ch * (128 * 128) + off) = __float2half_rn(v);
        } else if (idx < 128*128 + 128*256) {
            idx -= 128 * 128;
            int k = idx / 256, nn = idx % 256;
            float v = w1[(size_t)k * 256 + nn];
            int ch = k >> 6, kk = k & 63;
            uint32_t off = SWZ(nn * 128 + kk * 2);
            *(__half*)(g_B2 + (size_t)ch * (256 * 128) + off) = __float2half_rn(v);
        } else if (idx < BCONV_TOT) {
            idx -= 128*128 + 128*256;
            int k = idx / 128, nn = idx % 128;
            float v = w2[(size_t)k * 128 + nn];
            int ch = k >> 6, kk = k & 63;
            uint32_t off = SWZ(nn * 128 + kk * 2);
            *(__half*)(g_B3 + (size_t)ch * (128 * 128) + off) = __float2half_rn(v);
        }
        return;
    }
    int row  = (blockIdx.x - BCONV_BLK) * 8 + (threadIdx.x >> 5);
    int lane = threadIdx.x & 31;
    if (row >= n) return;
    const float4 v = *(const float4*)&in[(size_t)row * DIN + lane * 4];
    float s  = warpSum(v.x + v.y + v.z + v.w);
    float sq = warpSum(v.x * v.x + v.y * v.y + v.z * v.z + v.w * v.w);
    float m = s * (1.f / DIN);
    float inv = rsqrtf(sq * (1.f / DIN) - m * m + EPSV);
    const float4 g = *(const float4*)&gg[lane * 4];
    const float4 b = *(const float4*)&bb[lane * 4];
    float4 o;
    o.x = (v.x - m) * inv * g.x + b.x;
    o.y = (v.y - m) * inv * g.y + b.y;
    o.z = (v.z - m) * inv * g.z + b.z;
    o.w = (v.w - m) * inv * g.w + b.w;
    int mtile = row >> 7, r = row & 127;
    int col0 = lane * 4, ch = col0 >> 6, kk = col0 & 63;
    uint32_t off = SWZ(r * 128 + kk * 2);
    char* base = g_A1 + (size_t)mtile * (2 * 2 * 16384);
    split_store8h(base, (size_t)(0 * 2 + ch) * 16384, (size_t)(1 * 2 + ch) * 16384, off, o);
}

// ---------------- warp-MMA GEMM, 64x128 block tile, 2 CTAs/SM -----------------
// fp16: A hi/lo x B single, 2-MMA compensation.
// EPI 0: fp16 xh table + attention logits. EPI 1: gelu -> A3 fp16 image. EPI 2: +bias+resid.
template <int NTOT, int NCH, int EPI>
__global__ void __launch_bounds__(256, 2)
mma_gemm(const char* __restrict__ Aimg, const char* __restrict__ Bimg,
         const float* __restrict__ bias, const float* __restrict__ resid,
         float* __restrict__ outF, char* __restrict__ outImg,
         const float* __restrict__ attS, const float* __restrict__ attD, int M) {
    extern __shared__ char smem[];
    const uint32_t sb = smem_u32(smem);
    const int tid = threadIdx.x, wid = tid >> 5, lane = tid & 31;
    const int mblk = blockIdx.x, nb = blockIdx.y;
    const int mtile128 = mblk >> 1, mhalf = mblk & 1;
    const int wm = wid & 1, wn = wid >> 1;
    constexpr int BUFS = 32768;   // stage bytes: Ah 8K + Al 8K + B 16K

    const char* Ab = Aimg + (size_t)mtile128 * (2 * NCH * 16384) + (size_t)mhalf * 8192;

    int rowTA[2], rowTB[2];
#pragma unroll
    for (int mf = 0; mf < 2; mf++)
        rowTA[mf] = (wm * 32 + mf * 16 + (lane & 15)) * 128 + (lane >> 4) * 16;
#pragma unroll
    for (int nfg = 0; nfg < 2; nfg++)
        rowTB[nfg] = (wn * 32 + nfg * 16 + (lane >> 4) * 8 + (lane & 7)) * 128
                   + ((lane >> 3) & 1) * 16;

    float acc[2][4][4];
#pragma unroll
    for (int i = 0; i < 2; i++)
#pragma unroll
        for (int j = 0; j < 4; j++)
#pragma unroll
            for (int q = 0; q < 4; q++) acc[i][j][q] = 0.f;

    auto stage = [&](int c, int bufIdx) {
        const char* aSrc[2] = {
            Ab + (size_t)(0 * NCH + c) * 16384,
            Ab + (size_t)(1 * NCH + c) * 16384
        };
        uint32_t dbase = sb + bufIdx * BUFS;
#pragma unroll
        for (int sel = 0; sel < 2; sel++) {
#pragma unroll
            for (int i = 0; i < 2; i++) {
                int ofs = (tid + 256 * i) * 16;
                cpasync16(dbase + sel * 8192 + ofs, aSrc[sel] + ofs);
            }
        }
        const char* bSrc = Bimg + (size_t)c * ((size_t)NTOT * 128) + (size_t)nb * 16384;
#pragma unroll
        for (int i = 0; i < 4; i++) {
            int ofs = (tid + 256 * i) * 16;
            cpasync16(dbase + 16384 + ofs, bSrc + ofs);
        }
        asm volatile("cp.async.commit_group;" ::: "memory");
    };

    stage(0, 0);
    int buf = 0;
    for (int c = 0; c < NCH; c++) {
        if (c + 1 < NCH) {
            stage(c + 1, buf ^ 1);
            asm volatile("cp.async.wait_group 1;" ::: "memory");
        } else {
            asm volatile("cp.async.wait_group 0;" ::: "memory");
        }
        __syncthreads();

        const uint32_t bbase = sb + buf * BUFS;
#pragma unroll
        for (int kk = 0; kk < 4; kk++) {
            uint32_t ah[2][4], al[2][4];
#pragma unroll
            for (int mf = 0; mf < 2; mf++) {
                uint32_t off = SWZ(rowTA[mf] + kk * 32);
                ldsm4(ah[mf], bbase + off);
                ldsm4(al[mf], bbase + 8192 + off);
            }
#pragma unroll
            for (int nfg = 0; nfg < 2; nfg++) {
                uint32_t off = SWZ(rowTB[nfg] + kk * 32);
                uint32_t bq[4];
                ldsm4(bq, bbase + 16384 + off);
#pragma unroll
                for (int mf = 0; mf < 2; mf++) {
                    mma16816h(acc[mf][2 * nfg],     ah[mf], bq);
                    mma16816h(acc[mf][2 * nfg],     al[mf], bq);
                    mma16816h(acc[mf][2 * nfg + 1], ah[mf], bq + 2);
                    mma16816h(acc[mf][2 * nfg + 1], al[mf], bq + 2);
                }
            }
        }
        __syncthreads();
        buf ^= 1;
    }

    // ---------------- epilogue ----------------
#pragma unroll
    for (int mf = 0; mf < 2; mf++) {
        const int rl0 = wm * 32 + mf * 16 + (lane >> 2);   // local row 0..63
        const int m0 = mblk * 64 + rl0;
        const int m1 = m0 + 8;
        float ps0 = 0.f, pd0 = 0.f, ps1 = 0.f, pd1 = 0.f;
#pragma unroll
        for (int nfr = 0; nfr < 4; nfr++) {
            const int col = nb * 128 + wn * 32 + nfr * 8 + (lane & 3) * 2;
            float* cc = acc[mf][nfr];
            if (EPI == 0) {
                const float as0 = attS[col], as1 = attS[col + 1];
                const float ad0 = attD[col], ad1 = attD[col + 1];
                ps0 += cc[0] * as0 + cc[1] * as1;
                pd0 += cc[0] * ad0 + cc[1] * ad1;
                ps1 += cc[2] * as0 + cc[3] * as1;
                pd1 += cc[2] * ad0 + cc[3] * ad1;
                __half2 v0 = __floats2half2_rn(cc[0], cc[1]);
                __half2 v1 = __floats2half2_rn(cc[2], cc[3]);
                if (m0 < M) *(__half2*)&g_xhh[(size_t)m0 * DIN + col] = v0;
                if (m1 < M) *(__half2*)&g_xhh[(size_t)m1 * DIN + col] = v1;
            } else if (EPI == 1) {
                char* img = outImg + (size_t)mtile128 * (2 * 4 * 16384);
                const int ir0 = mhalf * 64 + rl0;           // image row 0..127
                const float b0 = bias[col], b1 = bias[col + 1];
                const int ch = col >> 6, kk = col & 63;
                const size_t hiOff = (size_t)(0 * 4 + ch) * 16384;
                const size_t loOff = (size_t)(1 * 4 + ch) * 16384;
                if (m0 < M) {
                    uint32_t hp, lp;
                    split2h(geluf(cc[0] + b0), geluf(cc[1] + b1), hp, lp);
                    uint32_t off = SWZ(ir0 * 128 + kk * 2);
                    *(uint32_t*)(img + hiOff + off) = hp;
                    *(uint32_t*)(img + loOff + off) = lp;
                }
                if (m1 < M) {
                    uint32_t hp, lp;
                    split2h(geluf(cc[2] + b0), geluf(cc[3] + b1), hp, lp);
                    uint32_t off = SWZ((ir0 + 8) * 128 + kk * 2);
                    *(uint32_t*)(img + hiOff + off) = hp;
                    *(uint32_t*)(img + loOff + off) = lp;
                }
            } else {
                const float b0 = bias[col], b1 = bias[col + 1];
                if (m0 < M) {
                    const float2 rr = *(const float2*)&resid[(size_t)m0 * NTOT + col];
                    *(float2*)&outF[(size_t)m0 * NTOT + col] =
                        make_float2(cc[0] + b0 + rr.x, cc[1] + b1 + rr.y);
                }
                if (m1 < M) {
                    const float2 rr = *(const float2*)&resid[(size_t)m1 * NTOT + col];
                    *(float2*)&outF[(size_t)m1 * NTOT + col] =
                        make_float2(cc[2] + b0 + rr.x, cc[3] + b1 + rr.y);
                }
            }
        }
        if (EPI == 0) {
#pragma unroll
            for (int o = 1; o <= 2; o <<= 1) {
                ps0 += __shfl_xor_sync(0xffffffffu, ps0, o);
                pd0 += __shfl_xor_sync(0xffffffffu, pd0, o);
                ps1 += __shfl_xor_sync(0xffffffffu, ps1, o);
                pd1 += __shfl_xor_sync(0xffffffffu, pd1, o);
            }
            if ((lane & 3) == 0) {
                if (m0 < M) {
                    g_asrc[m0 * NHEAD + wn] = ps0;
                    g_adst[m0 * NHEAD + wn] = pd0;
                }
                if (m1 < M) {
                    g_asrc[m1 * NHEAD + wn] = ps1;
                    g_adst[m1 * NHEAD + wn] = pd1;
                }
            }
        }
    }
}

// ---- fused gather aggregation: softmax + weighted sum + +gat_b + resid + LN2 -
// Software-pipelined: next edge's col + logit loaded before current FMA chain.
__global__ void csr_agg_kernel(const float* __restrict__ x,
                               const float* __restrict__ gat_b,
                               const float* __restrict__ g2,
                               const float* __restrict__ b2, int n, int Et) {
    int row  = blockIdx.x * 8 + (threadIdx.x >> 5);
    int lane = threadIdx.x & 31;
    if (row >= n) return;
    const int h = lane >> 3;
    const float adst_h = g_adst[row * NHEAD + h];
    const int p0 = g_rowp[row];
    const int p1 = (row == n - 1) ? Et : g_rowp[row + 1];

    float4 acc = make_float4(0.f, 0.f, 0.f, 0.f);
    float den = 0.f;
    int sCur = g_col[p0];                       // deg >= 1 (self loop)
    float aCur = g_asrc[sCur * NHEAD + h];
    for (int p = p0; p < p1; p++) {
        int sNext = 0; float aNext = 0.f;
        if (p + 1 < p1) {
            sNext = g_col[p + 1];
            aNext = g_asrc[sNext * NHEAD + h];
        }
        const uint2 raw = *(const uint2*)&g_xhh[(size_t)sCur * DIN + lane * 4];
        float ex = expf(lrelu(aCur + adst_h));
        den += ex;
        const float2 f0 = __half22float2(*(const __half2*)&raw.x);
        const float2 f1 = __half22float2(*(const __half2*)&raw.y);
        acc.x += f0.x * ex; acc.y += f0.y * ex;
        acc.z += f1.x * ex; acc.w += f1.y * ex;
        sCur = sNext; aCur = aNext;
    }
    float inv = 1.f / den;
    const float4 xv = *(const float4*)&x[(size_t)row * DIN + lane * 4];
    const float4 gb = *(const float4*)&gat_b[lane * 4];
    float4 h2;
    h2.x = acc.x * inv + gb.x + xv.x;
    h2.y = acc.y * inv + gb.y + xv.y;
    h2.z = acc.z * inv + gb.z + xv.z;
    h2.w = acc.w * inv + gb.w + xv.w;
    *(float4*)&g_h2[(size_t)row * DIN + lane * 4] = h2;

    float s  = warpSum(h2.x + h2.y + h2.z + h2.w);
    float sq = warpSum(h2.x * h2.x + h2.y * h2.y + h2.z * h2.z + h2.w * h2.w);
    float m = s * (1.f / DIN);
    float rin = rsqrtf(sq * (1.f / DIN) - m * m + EPSV);
    const float4 g = *(const float4*)&g2[lane * 4];
    const float4 b = *(const float4*)&b2[lane * 4];
    float4 o;
    o.x = (h2.x - m) * rin * g.x + b.x;
    o.y = (h2.y - m) * rin * g.y + b.y;
    o.z = (h2.z - m) * rin * g.z + b.z;
    o.w = (h2.w - m) * rin * g.w + b.w;
    int mtile = row >> 7, r = row & 127;
    int col0 = lane * 4, ch = col0 >> 6, kk = col0 & 63;
    uint32_t off = SWZ(r * 128 + kk * 2);
    char* base = g_A2 + (size_t)mtile * (2 * 2 * 16384);
    split_store8h(base, (size_t)(0 * 2 + ch) * 16384, (size_t)(1 * 2 + ch) * 16384, off, o);
}

// ---------------- launch ------------------------------------------------------
extern "C" void kernel_launch(void* const* d_in, const int* in_sizes, int n_in,
                              void* d_out, int out_size) {
    const float* x     = (const float*)d_in[0];
    const void*  ei    = d_in[1];
    const float* ln1_g = (const float*)d_in[2];
    const float* ln1_b = (const float*)d_in[3];
    const float* W     = (const float*)d_in[4];
    const float* att_s = (const float*)d_in[5];
    const float* att_d = (const float*)d_in[6];
    const float* gat_b = (const float*)d_in[7];
    const float* ln2_g = (const float*)d_in[8];
    const float* ln2_b = (const float*)d_in[9];
    const float* w1    = (const float*)d_in[10];
    const float* b1    = (const float*)d_in[11];
    const float* w2    = (const float*)d_in[12];
    const float* b2    = (const float*)d_in[13];
    float*       out   = (float*)d_out;

    const int n      = in_sizes[0] / DIN;
    const int E      = in_sizes[1] / 2;
    const int Et     = E + n;
    const int mtiles = (n + 127) / 128;
    const int mblks  = 2 * mtiles;
    const int nparts = (n + 1023) / 1024;

    float* ph2;  cudaGetSymbolAddress((void**)&ph2, g_h2);
    char*  pA1;  cudaGetSymbolAddress((void**)&pA1, g_A1);
    char*  pA2;  cudaGetSymbolAddress((void**)&pA2, g_A2);
    char*  pA3;  cudaGetSymbolAddress((void**)&pA3, g_A3);
    char*  pB1;  cudaGetSymbolAddress((void**)&pB1, g_B1);
    char*  pB2;  cudaGetSymbolAddress((void**)&pB2, g_B2);
    char*  pB3;  cudaGetSymbolAddress((void**)&pB3, g_B3);

    const int SMEM = 65536;   // fp16: 2 x 32KB double-buffered -> 2 CTAs/SM
    cudaFuncSetAttribute(mma_gemm<128, 2, 0>, cudaFuncAttributeMaxDynamicSharedMemorySize, SMEM);
    cudaFuncSetAttribute(mma_gemm<256, 2, 1>, cudaFuncAttributeMaxDynamicSharedMemorySize, SMEM);
    cudaFuncSetAttribute(mma_gemm<128, 4, 2>, cudaFuncAttributeMaxDynamicSharedMemorySize, SMEM);

    // one-time resources (host-side only; no device memory)
    static cudaStream_t s2 = nullptr;
    static cudaEvent_t evFork = nullptr, evCsr = nullptr;
    if (!s2) {
        cudaStreamCreateWithFlags(&s2, cudaStreamNonBlocking);
        cudaEventCreateWithFlags(&evFork, cudaEventDisableTiming);
        cudaEventCreateWithFlags(&evCsr, cudaEventDisableTiming);
    }

    // fork: CSR build on side stream. g_cnt is zero on entry (zero-init on
    // first run; re-zeroed by scatter_kernel on every replay).
    cudaEventRecord(evFork, 0);
    cudaStreamWaitEvent(s2, evFork, 0);
    count_kernel<<<(Et + 255) / 256, 256, 0, s2>>>(ei, E, Et);
    scan_kernel<<<nparts, 256, 0, s2>>>(n);
    scatter_kernel<<<(Et + 255) / 256, 256, 0, s2>>>(Et, n);
    cudaEventRecord(evCsr, s2);

    // main path
    bconv_ln_kernel<<<BCONV_BLK + (n + 7) / 8, 256>>>(W, w1, w2, x, ln1_g, ln1_b, n);
    mma_gemm<128, 2, 0><<<dim3(mblks, 1), 256, SMEM>>>(
        pA1, pB1, nullptr, nullptr, nullptr, nullptr, att_s, att_d, n);

    // join: csr_agg needs both CSR and GEMM1 outputs
    cudaStreamWaitEvent(0, evCsr, 0);
    csr_agg_kernel<<<(n + 7) / 8, 256>>>(x, gat_b, ln2_g, ln2_b, n, Et);
    mma_gemm<256, 2, 1><<<dim3(mblks, 2), 256, SMEM>>>(
        pA2, pB2, b1, nullptr, nullptr, pA3, nullptr, nullptr, n);
    mma_gemm<128, 4, 2><<<dim3(mblks, 1), 256, SMEM>>>(
        pA3, pB3, b2, ph2, out, nullptr, nullptr, nullptr, n);
}